// round 1
// baseline (speedup 1.0000x reference)
#include <cuda_runtime.h>
#include <cuda_bf16.h>
#include <cstddef>

// Problem dims (fixed)
#define B_DIM 1024
#define M_DIM 4096
#define W_DIM 2
#define L_DIM 2
#define Z_DIM 64
#define H_DIM 8192   // M*W

// Output layout: x_recon [B*M], logcov [B*M], mu [B*Z], logvar [B*Z]
#define OFF_XREC  0
#define OFF_LCOV  (B_DIM * M_DIM)
#define OFF_MU    (2 * B_DIM * M_DIM)
#define OFF_LV    (2 * B_DIM * M_DIM + B_DIM * Z_DIM)

// -------- scratch (no allocations allowed; __device__ globals) --------
__device__ float g_h1[B_DIM * M_DIM];     // encoder layer-1 out
__device__ float g_h2[B_DIM * M_DIM];     // encoder layer-2 out
__device__ float g_mulv[B_DIM * 128];     // [b][0:64]=mu pre, [64:128]=logvar pre
__device__ float g_z[B_DIM * Z_DIM];
__device__ float g_am[B_DIM * H_DIM];     // mean branch fulcon activations
__device__ float g_ac[B_DIM * H_DIM];     // cov  branch fulcon activations

__device__ __forceinline__ float sigm(float x) { return 1.0f / (1.0f + expf(-x)); }

// ===================== generic tiled GEMM: C = act(A * W^T + bias) =====================
// A: [Mdim, Kdim] row-major, W: [Ndim, Kdim] row-major (both K contiguous)
// BM=128, BN=128, BK=16, 256 threads, each thread 8x8.
#define ACT_RELU 1
#define ACT_SIGMOID 2

template <int ACT>
__global__ void __launch_bounds__(256) gemm_nt_kernel(
    const float* __restrict__ A, const float* __restrict__ Wt,
    const float* __restrict__ bias, float* __restrict__ C,
    int Mdim, int Ndim, int Kdim)
{
    __shared__ float As[16][128];
    __shared__ float Ws[16][128];

    const int tid = threadIdx.x;
    const int tx  = tid & 15;    // n direction
    const int ty  = tid >> 4;    // m direction
    const int m0  = blockIdx.y * 128;
    const int n0  = blockIdx.x * 128;

    float acc[8][8];
#pragma unroll
    for (int i = 0; i < 8; i++)
#pragma unroll
        for (int j = 0; j < 8; j++) acc[i][j] = 0.0f;

    for (int k0 = 0; k0 < Kdim; k0 += 16) {
        // load A tile (128 rows x 16 k): 512 float4, 2 per thread, store transposed
#pragma unroll
        for (int it = 0; it < 2; it++) {
            int idx = tid + it * 256;            // 0..511
            int row = idx >> 2;
            int kq  = (idx & 3) * 4;
            float4 v = *reinterpret_cast<const float4*>(
                &A[(size_t)(m0 + row) * Kdim + k0 + kq]);
            As[kq + 0][row] = v.x;
            As[kq + 1][row] = v.y;
            As[kq + 2][row] = v.z;
            As[kq + 3][row] = v.w;
        }
#pragma unroll
        for (int it = 0; it < 2; it++) {
            int idx = tid + it * 256;
            int row = idx >> 2;
            int kq  = (idx & 3) * 4;
            float4 v = *reinterpret_cast<const float4*>(
                &Wt[(size_t)(n0 + row) * Kdim + k0 + kq]);
            Ws[kq + 0][row] = v.x;
            Ws[kq + 1][row] = v.y;
            Ws[kq + 2][row] = v.z;
            Ws[kq + 3][row] = v.w;
        }
        __syncthreads();

#pragma unroll
        for (int k = 0; k < 16; k++) {
            float ar[8], br[8];
            *reinterpret_cast<float4*>(&ar[0]) = *reinterpret_cast<const float4*>(&As[k][ty * 8]);
            *reinterpret_cast<float4*>(&ar[4]) = *reinterpret_cast<const float4*>(&As[k][ty * 8 + 4]);
            *reinterpret_cast<float4*>(&br[0]) = *reinterpret_cast<const float4*>(&Ws[k][tx * 8]);
            *reinterpret_cast<float4*>(&br[4]) = *reinterpret_cast<const float4*>(&Ws[k][tx * 8 + 4]);
#pragma unroll
            for (int i = 0; i < 8; i++)
#pragma unroll
                for (int j = 0; j < 8; j++)
                    acc[i][j] = fmaf(ar[i], br[j], acc[i][j]);
        }
        __syncthreads();
    }

    // epilogue
#pragma unroll
    for (int i = 0; i < 8; i++) {
        int m = m0 + ty * 8 + i;
#pragma unroll
        for (int j = 0; j < 8; j++) {
            int n = n0 + tx * 8 + j;
            float v = acc[i][j] + bias[n];
            if (ACT == ACT_RELU)    v = fmaxf(v, 0.0f);
            if (ACT == ACT_SIGMOID) v = sigm(v);
            C[(size_t)m * Ndim + n] = v;
        }
    }
}

// ===================== mu / logvar projection =====================
// grid (B/2, 16), 256 threads = 8 warps. Each warp computes one output j
// (j<64 -> mu, else logvar) for 2 batch rows staged in shared memory.
__global__ void __launch_bounds__(256) mulv_kernel(
    const float* __restrict__ h2,
    const float* __restrict__ mu_w, const float* __restrict__ mu_b,
    const float* __restrict__ lv_w, const float* __restrict__ lv_b,
    float* __restrict__ mulv)
{
    __shared__ float sh[2][4096];
    const int b0  = blockIdx.x * 2;
    const int tid = threadIdx.x;

    for (int i = tid; i < 2048; i += 256) {          // 2048 float4 = 2 rows
        int r = i >> 10, c = (i & 1023) * 4;
        *reinterpret_cast<float4*>(&sh[r][c]) =
            *reinterpret_cast<const float4*>(&h2[(size_t)(b0 + r) * 4096 + c]);
    }
    __syncthreads();

    const int warp = tid >> 5, lane = tid & 31;
    const int j = blockIdx.y * 8 + warp;             // 0..127
    const float* wr = (j < 64) ? (mu_w + (size_t)j * 4096)
                               : (lv_w + (size_t)(j - 64) * 4096);
    const float bj = (j < 64) ? mu_b[j] : lv_b[j - 64];

    float acc0 = 0.0f, acc1 = 0.0f;
#pragma unroll 4
    for (int it = 0; it < 32; it++) {
        int k = it * 128 + lane * 4;
        float4 w  = *reinterpret_cast<const float4*>(&wr[k]);
        float4 x0 = *reinterpret_cast<const float4*>(&sh[0][k]);
        float4 x1 = *reinterpret_cast<const float4*>(&sh[1][k]);
        acc0 = fmaf(w.x, x0.x, fmaf(w.y, x0.y, fmaf(w.z, x0.z, fmaf(w.w, x0.w, acc0))));
        acc1 = fmaf(w.x, x1.x, fmaf(w.y, x1.y, fmaf(w.z, x1.z, fmaf(w.w, x1.w, acc1))));
    }
#pragma unroll
    for (int off = 16; off > 0; off >>= 1) {
        acc0 += __shfl_xor_sync(0xffffffffu, acc0, off);
        acc1 += __shfl_xor_sync(0xffffffffu, acc1, off);
    }
    if (lane == 0) {
        mulv[(size_t)b0 * 128 + j]       = acc0 + bj;
        mulv[(size_t)(b0 + 1) * 128 + j] = acc1 + bj;
    }
}

// ===================== reparameterization + mu/logvar output =====================
__global__ void z_kernel(const float* __restrict__ mulv, const float* __restrict__ eps,
                         float* __restrict__ z, float* __restrict__ out)
{
    int idx = blockIdx.x * 256 + threadIdx.x;        // < B*Z = 65536
    if (idx >= B_DIM * Z_DIM) return;
    int b = idx >> 6, j = idx & 63;
    float mu = mulv[(size_t)b * 128 + j];
    float lv = mulv[(size_t)b * 128 + 64 + j];
    z[idx] = mu + expf(0.5f * lv) * eps[idx];
    out[OFF_MU + idx] = mu;
    out[OFF_LV + idx] = lv;
}

// ===================== decoder tail: block-diagonal layers + output =====================
// one thread per (b, m); both branches fused.
__global__ void __launch_bounds__(256) tail_kernel(
    const float* __restrict__ am, const float* __restrict__ ac,
    const float* __restrict__ mhw, const float* __restrict__ mhb,
    const float* __restrict__ mow, const float* __restrict__ mob,
    const float* __restrict__ chw, const float* __restrict__ chb,
    const float* __restrict__ cow, const float* __restrict__ cob,
    float* __restrict__ out)
{
    int idx = blockIdx.x * 256 + threadIdx.x;        // b*4096 + m
    if (idx >= B_DIM * M_DIM) return;
    int b = idx >> 12, m = idx & 4095;

    // ---- mean branch ----
    {
        float2 a = *reinterpret_cast<const float2*>(&am[(size_t)b * H_DIM + 2 * m]);
        float a0 = a.x, a1 = a.y;
#pragma unroll
        for (int l = 0; l < L_DIM; l++) {
            float4 w = *reinterpret_cast<const float4*>(&mhw[((size_t)l * M_DIM + m) * 4]);
            float b0v = mhb[l * H_DIM + 2 * m];
            float b1v = mhb[l * H_DIM + 2 * m + 1];
            float n0 = sigm(fmaf(a0, w.x, fmaf(a1, w.y, b0v)));
            float n1 = sigm(fmaf(a0, w.z, fmaf(a1, w.w, b1v)));
            a0 = n0; a1 = n1;
        }
        float2 ow = *reinterpret_cast<const float2*>(&mow[2 * m]);
        out[OFF_XREC + idx] = fmaf(a0, ow.x, fmaf(a1, ow.y, mob[m]));
    }
    // ---- logcov branch ----
    {
        float2 a = *reinterpret_cast<const float2*>(&ac[(size_t)b * H_DIM + 2 * m]);
        float a0 = a.x, a1 = a.y;
#pragma unroll
        for (int l = 0; l < L_DIM; l++) {
            float4 w = *reinterpret_cast<const float4*>(&chw[((size_t)l * M_DIM + m) * 4]);
            float b0v = chb[l * H_DIM + 2 * m];
            float b1v = chb[l * H_DIM + 2 * m + 1];
            float n0 = sigm(fmaf(a0, w.x, fmaf(a1, w.y, b0v)));
            float n1 = sigm(fmaf(a0, w.z, fmaf(a1, w.w, b1v)));
            a0 = n0; a1 = n1;
        }
        float2 ow = *reinterpret_cast<const float2*>(&cow[2 * m]);
        out[OFF_LCOV + idx] = fmaf(a0, ow.x, fmaf(a1, ow.y, cob[m]));
    }
}

// ===================== launch =====================
extern "C" void kernel_launch(void* const* d_in, const int* in_sizes, int n_in,
                              void* d_out, int out_size)
{
    const float* x        = (const float*)d_in[0];
    const float* eps      = (const float*)d_in[1];
    const float* enc1_w   = (const float*)d_in[2];
    const float* enc1_b   = (const float*)d_in[3];
    const float* enc2_w   = (const float*)d_in[4];
    const float* enc2_b   = (const float*)d_in[5];
    const float* mu_w     = (const float*)d_in[6];
    const float* mu_b     = (const float*)d_in[7];
    const float* lv_w     = (const float*)d_in[8];
    const float* lv_b     = (const float*)d_in[9];
    const float* m_ful_w  = (const float*)d_in[10];
    const float* m_ful_b  = (const float*)d_in[11];
    const float* m_h_w    = (const float*)d_in[12];
    const float* m_h_b    = (const float*)d_in[13];
    const float* m_out_w  = (const float*)d_in[14];
    const float* m_out_b  = (const float*)d_in[15];
    const float* c_ful_w  = (const float*)d_in[16];
    const float* c_ful_b  = (const float*)d_in[17];
    const float* c_h_w    = (const float*)d_in[18];
    const float* c_h_b    = (const float*)d_in[19];
    const float* c_out_w  = (const float*)d_in[20];
    const float* c_out_b  = (const float*)d_in[21];
    float* out = (float*)d_out;

    float *h1, *h2, *mulv, *z, *am, *ac;
    cudaGetSymbolAddress((void**)&h1,   g_h1);
    cudaGetSymbolAddress((void**)&h2,   g_h2);
    cudaGetSymbolAddress((void**)&mulv, g_mulv);
    cudaGetSymbolAddress((void**)&z,    g_z);
    cudaGetSymbolAddress((void**)&am,   g_am);
    cudaGetSymbolAddress((void**)&ac,   g_ac);

    // encoder
    dim3 g1(M_DIM / 128, B_DIM / 128);   // (32, 8)
    gemm_nt_kernel<ACT_RELU><<<g1, 256>>>(x,  enc1_w, enc1_b, h1, B_DIM, M_DIM, M_DIM);
    gemm_nt_kernel<ACT_RELU><<<g1, 256>>>(h1, enc2_w, enc2_b, h2, B_DIM, M_DIM, M_DIM);

    // mu / logvar
    dim3 g2(B_DIM / 2, 16);
    mulv_kernel<<<g2, 256>>>(h2, mu_w, mu_b, lv_w, lv_b, mulv);

    // reparameterization + mu/logvar outputs
    z_kernel<<<(B_DIM * Z_DIM + 255) / 256, 256>>>(mulv, eps, z, out);

    // decoder fulcon layers (sigmoid), K=64
    dim3 g3(H_DIM / 128, B_DIM / 128);   // (64, 8)
    gemm_nt_kernel<ACT_SIGMOID><<<g3, 256>>>(z, m_ful_w, m_ful_b, am, B_DIM, H_DIM, Z_DIM);
    gemm_nt_kernel<ACT_SIGMOID><<<g3, 256>>>(z, c_ful_w, c_ful_b, ac, B_DIM, H_DIM, Z_DIM);

    // decoder tail (both branches)
    tail_kernel<<<(B_DIM * M_DIM + 255) / 256, 256>>>(
        am, ac, m_h_w, m_h_b, m_out_w, m_out_b,
        c_h_w, c_h_b, c_out_w, c_out_b, out);
}

// round 2
// speedup vs baseline: 2.6064x; 2.6064x over previous
#include <cuda_runtime.h>
#include <cuda_bf16.h>
#include <cstdint>
#include <cstddef>

// Problem dims (fixed)
#define B_DIM 1024
#define M_DIM 4096
#define W_DIM 2
#define L_DIM 2
#define Z_DIM 64
#define H_DIM 8192   // M*W

// Output layout: x_recon [B*M], logcov [B*M], mu [B*Z], logvar [B*Z]
#define OFF_XREC  0
#define OFF_LCOV  (B_DIM * M_DIM)
#define OFF_MU    (2 * B_DIM * M_DIM)
#define OFF_LV    (2 * B_DIM * M_DIM + B_DIM * Z_DIM)

// -------- scratch (no allocations allowed; __device__ globals) --------
__device__ float g_h1[B_DIM * M_DIM];     // encoder layer-1 out
__device__ float g_h2[B_DIM * M_DIM];     // encoder layer-2 out
__device__ float g_mulv[B_DIM * 128];     // [b][0:64]=mu pre-bias, [64:128]=logvar pre-bias
__device__ float g_z[B_DIM * Z_DIM];
__device__ float g_am[B_DIM * H_DIM];     // mean branch fulcon activations
__device__ float g_ac[B_DIM * H_DIM];     // cov  branch fulcon activations

__device__ __forceinline__ float sigm(float x) { return 1.0f / (1.0f + expf(-x)); }

#define ACT_RELU 1
#define ACT_SIGMOID 2

// ===================== tf32 tensor-core GEMM: C = act(A * W^T + bias) =====================
// A: [Mdim, Kdim] row-major; W: [Ndim, Kdim] row-major. Kdim % 16 == 0,
// Mdim % 128 == 0, Ndim % 128 == 0.
// CTA tile 128x128, BK=16, 8 warps (warp tile 64x32), mma.m16n8k8.tf32,
// cp.async 2-stage pipeline.

__device__ __forceinline__ uint32_t f2tf32(float x) {
    uint32_t r;
    asm("cvt.rna.tf32.f32 %0, %1;" : "=r"(r) : "f"(x));
    return r;
}

__device__ __forceinline__ void mma_tf32(float* d, const uint32_t* a, const uint32_t* b) {
    asm volatile(
        "mma.sync.aligned.m16n8k8.row.col.f32.tf32.tf32.f32 "
        "{%0,%1,%2,%3}, {%4,%5,%6,%7}, {%8,%9}, {%0,%1,%2,%3};\n"
        : "+f"(d[0]), "+f"(d[1]), "+f"(d[2]), "+f"(d[3])
        : "r"(a[0]), "r"(a[1]), "r"(a[2]), "r"(a[3]), "r"(b[0]), "r"(b[1]));
}

__device__ __forceinline__ void cp_async16(uint32_t smem_addr, const void* gptr) {
    asm volatile("cp.async.cg.shared.global [%0], [%1], 16;\n"
                 :: "r"(smem_addr), "l"(gptr));
}
__device__ __forceinline__ void cp_commit() {
    asm volatile("cp.async.commit_group;\n");
}
template <int N>
__device__ __forceinline__ void cp_wait() {
    asm volatile("cp.async.wait_group %0;\n" :: "n"(N));
}

#define TF_LDA 20   // 16 + 4 pad (floats); stride 20 gives conflict-free frag reads

template <int ACT>
__global__ void __launch_bounds__(256, 2) gemm_tf32_kernel(
    const float* __restrict__ A, const float* __restrict__ Wt,
    const float* __restrict__ bias, float* __restrict__ C,
    int Mdim, int Ndim, int Kdim)
{
    __shared__ float sA[2][128 * TF_LDA];
    __shared__ float sB[2][128 * TF_LDA];

    const int tid  = threadIdx.x;
    const int lane = tid & 31;
    const int warp = tid >> 5;
    const int g    = lane >> 2;   // group id 0..7
    const int t    = lane & 3;    // thread-in-group 0..3
    const int wm   = (warp & 1) * 64;   // warp m offset in tile
    const int wn   = (warp >> 1) * 32;  // warp n offset in tile
    const int m0   = blockIdx.y * 128;
    const int n0   = blockIdx.x * 128;

    // cp.async source/dest for this thread: 2 chunks for A, 2 for B per stage.
    // chunk id c in 0..511: row = c>>2, koff = (c&3)*4
    const int c0row = tid >> 2,        c0k = (tid & 3) * 4;
    const int c1row = (tid + 256) >> 2, c1k = ((tid + 256) & 3) * 4;

    float acc[4][4][4];
#pragma unroll
    for (int i = 0; i < 4; i++)
#pragma unroll
        for (int j = 0; j < 4; j++)
#pragma unroll
            for (int r = 0; r < 4; r++) acc[i][j][r] = 0.0f;

    const int T = Kdim >> 4;   // number of BK=16 iterations

    auto load_tiles = [&](int it, int s) {
        int k0 = it << 4;
        uint32_t a0 = __cvta_generic_to_shared(&sA[s][c0row * TF_LDA + c0k]);
        uint32_t a1 = __cvta_generic_to_shared(&sA[s][c1row * TF_LDA + c1k]);
        uint32_t b0 = __cvta_generic_to_shared(&sB[s][c0row * TF_LDA + c0k]);
        uint32_t b1 = __cvta_generic_to_shared(&sB[s][c1row * TF_LDA + c1k]);
        cp_async16(a0, &A [(size_t)(m0 + c0row) * Kdim + k0 + c0k]);
        cp_async16(a1, &A [(size_t)(m0 + c1row) * Kdim + k0 + c1k]);
        cp_async16(b0, &Wt[(size_t)(n0 + c0row) * Kdim + k0 + c0k]);
        cp_async16(b1, &Wt[(size_t)(n0 + c1row) * Kdim + k0 + c1k]);
    };

    load_tiles(0, 0);
    cp_commit();

    for (int it = 0; it < T; ++it) {
        int s = it & 1;
        if (it + 1 < T) {
            load_tiles(it + 1, s ^ 1);
            cp_commit();
            cp_wait<1>();
        } else {
            cp_wait<0>();
        }
        __syncthreads();

        const float* As = sA[s];
        const float* Bs = sB[s];
#pragma unroll
        for (int k8 = 0; k8 < 16; k8 += 8) {
            uint32_t afr[4][4], bfr[4][2];
#pragma unroll
            for (int im = 0; im < 4; im++) {
                int r = wm + im * 16 + g;
                afr[im][0] = f2tf32(As[(r    ) * TF_LDA + k8 + t    ]);
                afr[im][1] = f2tf32(As[(r + 8) * TF_LDA + k8 + t    ]);
                afr[im][2] = f2tf32(As[(r    ) * TF_LDA + k8 + t + 4]);
                afr[im][3] = f2tf32(As[(r + 8) * TF_LDA + k8 + t + 4]);
            }
#pragma unroll
            for (int in_ = 0; in_ < 4; in_++) {
                int c = wn + in_ * 8 + g;
                bfr[in_][0] = f2tf32(Bs[c * TF_LDA + k8 + t    ]);
                bfr[in_][1] = f2tf32(Bs[c * TF_LDA + k8 + t + 4]);
            }
#pragma unroll
            for (int im = 0; im < 4; im++)
#pragma unroll
                for (int in_ = 0; in_ < 4; in_++)
                    mma_tf32(acc[im][in_], afr[im], bfr[in_]);
        }
        __syncthreads();
    }

    // epilogue: bias + activation, float2 stores (c0,c1 are adjacent columns)
#pragma unroll
    for (int im = 0; im < 4; im++) {
        int r0 = m0 + wm + im * 16 + g;
#pragma unroll
        for (int in_ = 0; in_ < 4; in_++) {
            int c = n0 + wn + in_ * 8 + t * 2;
            float b0v = bias[c], b1v = bias[c + 1];
            float v00 = acc[im][in_][0] + b0v;
            float v01 = acc[im][in_][1] + b1v;
            float v10 = acc[im][in_][2] + b0v;
            float v11 = acc[im][in_][3] + b1v;
            if (ACT == ACT_RELU) {
                v00 = fmaxf(v00, 0.0f); v01 = fmaxf(v01, 0.0f);
                v10 = fmaxf(v10, 0.0f); v11 = fmaxf(v11, 0.0f);
            }
            if (ACT == ACT_SIGMOID) {
                v00 = sigm(v00); v01 = sigm(v01);
                v10 = sigm(v10); v11 = sigm(v11);
            }
            *reinterpret_cast<float2*>(&C[(size_t)r0 * Ndim + c])       = make_float2(v00, v01);
            *reinterpret_cast<float2*>(&C[(size_t)(r0 + 8) * Ndim + c]) = make_float2(v10, v11);
        }
    }
}

// ===================== fp32 tiled GEMM (for K=64 fulcon layers) =====================
template <int ACT>
__global__ void __launch_bounds__(256) gemm_nt_kernel(
    const float* __restrict__ A, const float* __restrict__ Wt,
    const float* __restrict__ bias, float* __restrict__ C,
    int Mdim, int Ndim, int Kdim)
{
    __shared__ float As[16][128];
    __shared__ float Ws[16][128];

    const int tid = threadIdx.x;
    const int tx  = tid & 15;
    const int ty  = tid >> 4;
    const int m0  = blockIdx.y * 128;
    const int n0  = blockIdx.x * 128;

    float acc[8][8];
#pragma unroll
    for (int i = 0; i < 8; i++)
#pragma unroll
        for (int j = 0; j < 8; j++) acc[i][j] = 0.0f;

    for (int k0 = 0; k0 < Kdim; k0 += 16) {
#pragma unroll
        for (int it = 0; it < 2; it++) {
            int idx = tid + it * 256;
            int row = idx >> 2;
            int kq  = (idx & 3) * 4;
            float4 v = *reinterpret_cast<const float4*>(
                &A[(size_t)(m0 + row) * Kdim + k0 + kq]);
            As[kq + 0][row] = v.x; As[kq + 1][row] = v.y;
            As[kq + 2][row] = v.z; As[kq + 3][row] = v.w;
        }
#pragma unroll
        for (int it = 0; it < 2; it++) {
            int idx = tid + it * 256;
            int row = idx >> 2;
            int kq  = (idx & 3) * 4;
            float4 v = *reinterpret_cast<const float4*>(
                &Wt[(size_t)(n0 + row) * Kdim + k0 + kq]);
            Ws[kq + 0][row] = v.x; Ws[kq + 1][row] = v.y;
            Ws[kq + 2][row] = v.z; Ws[kq + 3][row] = v.w;
        }
        __syncthreads();

#pragma unroll
        for (int k = 0; k < 16; k++) {
            float ar[8], br[8];
            *reinterpret_cast<float4*>(&ar[0]) = *reinterpret_cast<const float4*>(&As[k][ty * 8]);
            *reinterpret_cast<float4*>(&ar[4]) = *reinterpret_cast<const float4*>(&As[k][ty * 8 + 4]);
            *reinterpret_cast<float4*>(&br[0]) = *reinterpret_cast<const float4*>(&Ws[k][tx * 8]);
            *reinterpret_cast<float4*>(&br[4]) = *reinterpret_cast<const float4*>(&Ws[k][tx * 8 + 4]);
#pragma unroll
            for (int i = 0; i < 8; i++)
#pragma unroll
                for (int j = 0; j < 8; j++)
                    acc[i][j] = fmaf(ar[i], br[j], acc[i][j]);
        }
        __syncthreads();
    }

#pragma unroll
    for (int i = 0; i < 8; i++) {
        int m = m0 + ty * 8 + i;
#pragma unroll
        for (int j = 0; j < 8; j++) {
            int n = n0 + tx * 8 + j;
            float v = acc[i][j] + bias[n];
            if (ACT == ACT_RELU)    v = fmaxf(v, 0.0f);
            if (ACT == ACT_SIGMOID) v = sigm(v);
            C[(size_t)m * Ndim + n] = v;
        }
    }
}

// ===================== mu / logvar projection (tiled, K-split, atomic accumulate) ===========
// grid (B/64, 128/16, 4); block 256. Tile: 64 batches x 16 outputs, K chunk 1024.
// mulv must be zeroed before launch; biases added later in z_kernel.
__global__ void __launch_bounds__(256) mulv_kernel(
    const float* __restrict__ h2,
    const float* __restrict__ mu_w, const float* __restrict__ lv_w,
    float* __restrict__ mulv)
{
    __shared__ float Hs[64][36];
    __shared__ float Ws_[16][36];

    const int tid = threadIdx.x;
    const int b0  = blockIdx.x * 64;
    const int j0  = blockIdx.y * 16;
    const int kb  = blockIdx.z * 1024;

    const int tj  = tid & 15;        // output j within tile
    const int tb4 = (tid >> 4) * 4;  // 4 batch rows per thread

    float a0 = 0.0f, a1 = 0.0f, a2 = 0.0f, a3 = 0.0f;

    for (int kt = 0; kt < 32; kt++) {
        int k0 = kb + kt * 32;
        // load Hs: 64 rows x 32 k = 512 float4, 2 per thread
#pragma unroll
        for (int it = 0; it < 2; it++) {
            int c = tid + it * 256;
            int row = c >> 3, coff = (c & 7) * 4;
            *reinterpret_cast<float4*>(&Hs[row][coff]) =
                *reinterpret_cast<const float4*>(&h2[(size_t)(b0 + row) * 4096 + k0 + coff]);
        }
        // load Ws_: 16 rows x 32 k = 128 float4, threads 0..127
        if (tid < 128) {
            int row = tid >> 3, coff = (tid & 7) * 4;
            int jg = j0 + row;
            const float* wr = (jg < 64) ? (mu_w + (size_t)jg * 4096)
                                        : (lv_w + (size_t)(jg - 64) * 4096);
            *reinterpret_cast<float4*>(&Ws_[row][coff]) =
                *reinterpret_cast<const float4*>(&wr[k0 + coff]);
        }
        __syncthreads();

#pragma unroll
        for (int k = 0; k < 32; k += 4) {
            float4 w  = *reinterpret_cast<const float4*>(&Ws_[tj][k]);
            float4 h0 = *reinterpret_cast<const float4*>(&Hs[tb4 + 0][k]);
            float4 h1v= *reinterpret_cast<const float4*>(&Hs[tb4 + 1][k]);
            float4 h2v= *reinterpret_cast<const float4*>(&Hs[tb4 + 2][k]);
            float4 h3 = *reinterpret_cast<const float4*>(&Hs[tb4 + 3][k]);
            a0 = fmaf(w.x, h0.x, fmaf(w.y, h0.y, fmaf(w.z, h0.z, fmaf(w.w, h0.w, a0))));
            a1 = fmaf(w.x, h1v.x, fmaf(w.y, h1v.y, fmaf(w.z, h1v.z, fmaf(w.w, h1v.w, a1))));
            a2 = fmaf(w.x, h2v.x, fmaf(w.y, h2v.y, fmaf(w.z, h2v.z, fmaf(w.w, h2v.w, a2))));
            a3 = fmaf(w.x, h3.x, fmaf(w.y, h3.y, fmaf(w.z, h3.z, fmaf(w.w, h3.w, a3))));
        }
        __syncthreads();
    }

    atomicAdd(&mulv[(size_t)(b0 + tb4 + 0) * 128 + j0 + tj], a0);
    atomicAdd(&mulv[(size_t)(b0 + tb4 + 1) * 128 + j0 + tj], a1);
    atomicAdd(&mulv[(size_t)(b0 + tb4 + 2) * 128 + j0 + tj], a2);
    atomicAdd(&mulv[(size_t)(b0 + tb4 + 3) * 128 + j0 + tj], a3);
}

// ===================== reparameterization + mu/logvar output (adds bias) =====================
__global__ void z_kernel(const float* __restrict__ mulv, const float* __restrict__ eps,
                         const float* __restrict__ mu_b, const float* __restrict__ lv_b,
                         float* __restrict__ z, float* __restrict__ out)
{
    int idx = blockIdx.x * 256 + threadIdx.x;
    if (idx >= B_DIM * Z_DIM) return;
    int b = idx >> 6, j = idx & 63;
    float mu = mulv[(size_t)b * 128 + j]      + mu_b[j];
    float lv = mulv[(size_t)b * 128 + 64 + j] + lv_b[j];
    z[idx] = mu + expf(0.5f * lv) * eps[idx];
    out[OFF_MU + idx] = mu;
    out[OFF_LV + idx] = lv;
}

// ===================== decoder tail: block-diagonal layers + output =====================
__global__ void __launch_bounds__(256) tail_kernel(
    const float* __restrict__ am, const float* __restrict__ ac,
    const float* __restrict__ mhw, const float* __restrict__ mhb,
    const float* __restrict__ mow, const float* __restrict__ mob,
    const float* __restrict__ chw, const float* __restrict__ chb,
    const float* __restrict__ cow, const float* __restrict__ cob,
    float* __restrict__ out)
{
    int idx = blockIdx.x * 256 + threadIdx.x;
    if (idx >= B_DIM * M_DIM) return;
    int b = idx >> 12, m = idx & 4095;

    {
        float2 a = *reinterpret_cast<const float2*>(&am[(size_t)b * H_DIM + 2 * m]);
        float a0 = a.x, a1 = a.y;
#pragma unroll
        for (int l = 0; l < L_DIM; l++) {
            float4 w = *reinterpret_cast<const float4*>(&mhw[((size_t)l * M_DIM + m) * 4]);
            float b0v = mhb[l * H_DIM + 2 * m];
            float b1v = mhb[l * H_DIM + 2 * m + 1];
            float n0 = sigm(fmaf(a0, w.x, fmaf(a1, w.y, b0v)));
            float n1 = sigm(fmaf(a0, w.z, fmaf(a1, w.w, b1v)));
            a0 = n0; a1 = n1;
        }
        float2 ow = *reinterpret_cast<const float2*>(&mow[2 * m]);
        out[OFF_XREC + idx] = fmaf(a0, ow.x, fmaf(a1, ow.y, mob[m]));
    }
    {
        float2 a = *reinterpret_cast<const float2*>(&ac[(size_t)b * H_DIM + 2 * m]);
        float a0 = a.x, a1 = a.y;
#pragma unroll
        for (int l = 0; l < L_DIM; l++) {
            float4 w = *reinterpret_cast<const float4*>(&chw[((size_t)l * M_DIM + m) * 4]);
            float b0v = chb[l * H_DIM + 2 * m];
            float b1v = chb[l * H_DIM + 2 * m + 1];
            float n0 = sigm(fmaf(a0, w.x, fmaf(a1, w.y, b0v)));
            float n1 = sigm(fmaf(a0, w.z, fmaf(a1, w.w, b1v)));
            a0 = n0; a1 = n1;
        }
        float2 ow = *reinterpret_cast<const float2*>(&cow[2 * m]);
        out[OFF_LCOV + idx] = fmaf(a0, ow.x, fmaf(a1, ow.y, cob[m]));
    }
}

// ===================== launch =====================
extern "C" void kernel_launch(void* const* d_in, const int* in_sizes, int n_in,
                              void* d_out, int out_size)
{
    const float* x        = (const float*)d_in[0];
    const float* eps      = (const float*)d_in[1];
    const float* enc1_w   = (const float*)d_in[2];
    const float* enc1_b   = (const float*)d_in[3];
    const float* enc2_w   = (const float*)d_in[4];
    const float* enc2_b   = (const float*)d_in[5];
    const float* mu_w     = (const float*)d_in[6];
    const float* mu_b     = (const float*)d_in[7];
    const float* lv_w     = (const float*)d_in[8];
    const float* lv_b     = (const float*)d_in[9];
    const float* m_ful_w  = (const float*)d_in[10];
    const float* m_ful_b  = (const float*)d_in[11];
    const float* m_h_w    = (const float*)d_in[12];
    const float* m_h_b    = (const float*)d_in[13];
    const float* m_out_w  = (const float*)d_in[14];
    const float* m_out_b  = (const float*)d_in[15];
    const float* c_ful_w  = (const float*)d_in[16];
    const float* c_ful_b  = (const float*)d_in[17];
    const float* c_h_w    = (const float*)d_in[18];
    const float* c_h_b    = (const float*)d_in[19];
    const float* c_out_w  = (const float*)d_in[20];
    const float* c_out_b  = (const float*)d_in[21];
    float* out = (float*)d_out;

    float *h1, *h2, *mulv, *z, *am, *ac;
    cudaGetSymbolAddress((void**)&h1,   g_h1);
    cudaGetSymbolAddress((void**)&h2,   g_h2);
    cudaGetSymbolAddress((void**)&mulv, g_mulv);
    cudaGetSymbolAddress((void**)&z,    g_z);
    cudaGetSymbolAddress((void**)&am,   g_am);
    cudaGetSymbolAddress((void**)&ac,   g_ac);

    // encoder: tf32 tensor cores
    dim3 g1(M_DIM / 128, B_DIM / 128);   // (32, 8)
    gemm_tf32_kernel<ACT_RELU><<<g1, 256>>>(x,  enc1_w, enc1_b, h1, B_DIM, M_DIM, M_DIM);
    gemm_tf32_kernel<ACT_RELU><<<g1, 256>>>(h1, enc2_w, enc2_b, h2, B_DIM, M_DIM, M_DIM);

    // mu / logvar projection (zero, accumulate, then bias in z_kernel)
    cudaMemsetAsync(mulv, 0, B_DIM * 128 * sizeof(float), 0);
    dim3 g2(B_DIM / 64, 128 / 16, 4);
    mulv_kernel<<<g2, 256>>>(h2, mu_w, lv_w, mulv);

    z_kernel<<<(B_DIM * Z_DIM + 255) / 256, 256>>>(mulv, eps, mu_b, lv_b, z, out);

    // decoder fulcon layers (sigmoid), K=64 — fp32 path
    dim3 g3(H_DIM / 128, B_DIM / 128);   // (64, 8)
    gemm_nt_kernel<ACT_SIGMOID><<<g3, 256>>>(z, m_ful_w, m_ful_b, am, B_DIM, H_DIM, Z_DIM);
    gemm_nt_kernel<ACT_SIGMOID><<<g3, 256>>>(z, c_ful_w, c_ful_b, ac, B_DIM, H_DIM, Z_DIM);

    // decoder tail (both branches)
    tail_kernel<<<(B_DIM * M_DIM + 255) / 256, 256>>>(
        am, ac, m_h_w, m_h_b, m_out_w, m_out_b,
        c_h_w, c_h_b, c_out_w, c_out_b, out);
}

// round 4
// speedup vs baseline: 3.5331x; 1.3556x over previous
#include <cuda_runtime.h>
#include <cuda_fp16.h>
#include <cstdint>
#include <cstddef>

// Problem dims (fixed)
#define B_DIM 1024
#define M_DIM 4096
#define W_DIM 2
#define L_DIM 2
#define Z_DIM 64
#define H_DIM 8192   // M*W

// Output layout: x_recon [B*M], logcov [B*M], mu [B*Z], logvar [B*Z]
#define OFF_XREC  0
#define OFF_LCOV  (B_DIM * M_DIM)
#define OFF_MU    (2 * B_DIM * M_DIM)
#define OFF_LV    (2 * B_DIM * M_DIM + B_DIM * Z_DIM)

// -------- scratch (no allocations allowed; __device__ globals) --------
__device__ __half g_h1h[B_DIM * M_DIM];   // encoder layer-1 out (fp16)
__device__ float  g_h2[B_DIM * M_DIM];    // encoder layer-2 out (fp32)
__device__ float  g_mulv[B_DIM * 128];
__device__ float  g_z[B_DIM * Z_DIM];
__device__ float  g_am[B_DIM * H_DIM];
__device__ float  g_ac[B_DIM * H_DIM];

__device__ __forceinline__ float sigm(float x) { return 1.0f / (1.0f + expf(-x)); }

#define ACT_RELU 1
#define ACT_SIGMOID 2

// ===================== fp16 tensor-core GEMM: C = act(A * W^T + bias) =====================
// A: [Mrows, Kdim] (fp32 or fp16) row-major; Wt: [Ndim, Kdim] fp32 row-major.
// CTA tile 128x128, BK=32, 8 warps (warp tile 64x32), mma.m16n8k16.f16 with f32 accum.
// smem tiles fp16, row stride 80 bytes (40 halves) -> ldmatrix conflict-free.

__device__ __forceinline__ uint32_t smem_u32(const void* p) {
    uint32_t a;
    asm("{ .reg .u64 t; cvta.to.shared.u64 t, %1; cvt.u32.u64 %0, t; }" : "=r"(a) : "l"(p));
    return a;
}

__device__ __forceinline__ void ldmx4(uint32_t* r, uint32_t addr) {
    asm volatile("ldmatrix.sync.aligned.m8n8.x4.shared.b16 {%0,%1,%2,%3}, [%4];"
                 : "=r"(r[0]), "=r"(r[1]), "=r"(r[2]), "=r"(r[3]) : "r"(addr));
}
__device__ __forceinline__ void ldmx2(uint32_t* r, uint32_t addr) {
    asm volatile("ldmatrix.sync.aligned.m8n8.x2.shared.b16 {%0,%1}, [%2];"
                 : "=r"(r[0]), "=r"(r[1]) : "r"(addr));
}
__device__ __forceinline__ void mma_f16(float* d, const uint32_t* a, const uint32_t* b) {
    asm volatile(
        "mma.sync.aligned.m16n8k16.row.col.f32.f16.f16.f32 "
        "{%0,%1,%2,%3}, {%4,%5,%6,%7}, {%8,%9}, {%0,%1,%2,%3};\n"
        : "+f"(d[0]), "+f"(d[1]), "+f"(d[2]), "+f"(d[3])
        : "r"(a[0]), "r"(a[1]), "r"(a[2]), "r"(a[3]), "r"(b[0]), "r"(b[1]));
}
__device__ __forceinline__ uint32_t pack_h2(float lo, float hi) {
    __half2 h = __floats2half2_rn(lo, hi);
    return *reinterpret_cast<uint32_t*>(&h);
}

#define HS_ROW 80                 // bytes per smem row (40 halves: 32 data + 8 pad)
#define HS_TILE (128 * HS_ROW)    // 10240 B per matrix tile
#define HS_STAGE (2 * HS_TILE)    // A + B per stage

template <typename AT, typename OT, int ACT>
__global__ void __launch_bounds__(256, 2) gemm_h_kernel(
    const AT* __restrict__ A, const float* __restrict__ Wt,
    const float* __restrict__ bias, OT* __restrict__ C,
    int Ndim, int Kdim)
{
    __shared__ __align__(16) uint8_t sm[2][HS_STAGE];
    __shared__ float sbias[128];

    const int tid  = threadIdx.x;
    const int lane = tid & 31;
    const int warp = tid >> 5;
    const int wm   = (warp & 1) * 64;
    const int wn   = (warp >> 1) * 32;
    const int m0   = blockIdx.y * 128;
    const int n0   = blockIdx.x * 128;
    const uint32_t sb = smem_u32(sm);

    if (tid < 128) sbias[tid] = bias[n0 + tid];

    // ldmatrix per-lane byte offsets (within a tile, before row-block/kk offsets)
    const uint32_t a_lm = ((lane & 7) + ((lane >> 3) & 1) * 8) * HS_ROW + ((lane >> 4) & 1) * 16;
    const uint32_t b_lm = (lane & 7) * HS_ROW + ((lane >> 3) & 1) * 16;

    float acc[4][4][4];
#pragma unroll
    for (int i = 0; i < 4; i++)
#pragma unroll
        for (int j = 0; j < 4; j++)
#pragma unroll
            for (int r = 0; r < 4; r++) acc[i][j][r] = 0.0f;

    // ---- staging state (register prefetch) ----
    constexpr bool A_IS_HALF = (sizeof(AT) == 2);
    float4 ra[4];      // used when A is fp32
    uint4  rah[2];     // used when A is fp16
    float4 rb[4];

    auto loadA = [&](int it) {
        if (A_IS_HALF) {
#pragma unroll
            for (int i = 0; i < 2; i++) {
                int c = tid + i * 256;                       // 0..511
                int row = c >> 2, kc = (c & 3) * 8;          // halves
                rah[i] = *reinterpret_cast<const uint4*>(
                    reinterpret_cast<const __half*>(A) + (size_t)(m0 + row) * Kdim + it * 32 + kc);
            }
        } else {
#pragma unroll
            for (int i = 0; i < 4; i++) {
                int c = tid + i * 256;                       // 0..1023
                int row = c >> 3, kc = (c & 7) * 4;          // floats
                ra[i] = *reinterpret_cast<const float4*>(
                    reinterpret_cast<const float*>(A) + (size_t)(m0 + row) * Kdim + it * 32 + kc);
            }
        }
    };
    auto loadB = [&](int it) {
#pragma unroll
        for (int i = 0; i < 4; i++) {
            int c = tid + i * 256;
            int row = c >> 3, kc = (c & 7) * 4;
            rb[i] = *reinterpret_cast<const float4*>(
                &Wt[(size_t)(n0 + row) * Kdim + it * 32 + kc]);
        }
    };
    auto stsAB = [&](int s) {
        uint8_t* base = &sm[s][0];
        if (A_IS_HALF) {
#pragma unroll
            for (int i = 0; i < 2; i++) {
                int c = tid + i * 256;
                int row = c >> 2, kc = (c & 3) * 8;
                *reinterpret_cast<uint4*>(base + row * HS_ROW + kc * 2) = rah[i];
            }
        } else {
#pragma unroll
            for (int i = 0; i < 4; i++) {
                int c = tid + i * 256;
                int row = c >> 3, kc = (c & 7) * 4;
                *reinterpret_cast<uint2*>(base + row * HS_ROW + kc * 2) =
                    make_uint2(pack_h2(ra[i].x, ra[i].y), pack_h2(ra[i].z, ra[i].w));
            }
        }
        uint8_t* bbase = base + HS_TILE;
#pragma unroll
        for (int i = 0; i < 4; i++) {
            int c = tid + i * 256;
            int row = c >> 3, kc = (c & 7) * 4;
            *reinterpret_cast<uint2*>(bbase + row * HS_ROW + kc * 2) =
                make_uint2(pack_h2(rb[i].x, rb[i].y), pack_h2(rb[i].z, rb[i].w));
        }
    };

    const int T = Kdim >> 5;   // BK = 32
    loadA(0); loadB(0);

    for (int it = 0; it < T; ++it) {
        const int s = it & 1;
        stsAB(s);
        __syncthreads();
        if (it + 1 < T) { loadA(it + 1); loadB(it + 1); }

        const uint32_t sa  = sb + s * HS_STAGE;
        const uint32_t sbm = sa + HS_TILE;
#pragma unroll
        for (int kk = 0; kk < 2; kk++) {
            uint32_t af[4][4], bf[4][2];
#pragma unroll
            for (int im = 0; im < 4; im++)
                ldmx4(af[im], sa + (wm + im * 16) * HS_ROW + a_lm + kk * 32);
#pragma unroll
            for (int in_ = 0; in_ < 4; in_++)
                ldmx2(bf[in_], sbm + (wn + in_ * 8) * HS_ROW + b_lm + kk * 32);
#pragma unroll
            for (int im = 0; im < 4; im++)
#pragma unroll
                for (int in_ = 0; in_ < 4; in_++)
                    mma_f16(acc[im][in_], af[im], bf[in_]);
        }
        __syncthreads();
    }

    // epilogue: bias + activation
    const int g = lane >> 2, t = lane & 3;
#pragma unroll
    for (int im = 0; im < 4; im++) {
        int r0 = m0 + wm + im * 16 + g;
#pragma unroll
        for (int in_ = 0; in_ < 4; in_++) {
            int cl = wn + in_ * 8 + t * 2;
            float b0v = sbias[cl], b1v = sbias[cl + 1];
            float v00 = acc[im][in_][0] + b0v;
            float v01 = acc[im][in_][1] + b1v;
            float v10 = acc[im][in_][2] + b0v;
            float v11 = acc[im][in_][3] + b1v;
            if (ACT == ACT_RELU) {
                v00 = fmaxf(v00, 0.0f); v01 = fmaxf(v01, 0.0f);
                v10 = fmaxf(v10, 0.0f); v11 = fmaxf(v11, 0.0f);
            }
            if (ACT == ACT_SIGMOID) {
                v00 = sigm(v00); v01 = sigm(v01);
                v10 = sigm(v10); v11 = sigm(v11);
            }
            int c = n0 + cl;
            if (sizeof(OT) == 2) {
                __half* Ch = reinterpret_cast<__half*>(C);
                __half2 lo = __floats2half2_rn(v00, v01);
                __half2 hi = __floats2half2_rn(v10, v11);
                *reinterpret_cast<__half2*>(&Ch[(size_t)r0 * Ndim + c]) = lo;
                *reinterpret_cast<__half2*>(&Ch[(size_t)(r0 + 8) * Ndim + c]) = hi;
            } else {
                float* Cf = reinterpret_cast<float*>(C);
                *reinterpret_cast<float2*>(&Cf[(size_t)r0 * Ndim + c]) = make_float2(v00, v01);
                *reinterpret_cast<float2*>(&Cf[(size_t)(r0 + 8) * Ndim + c]) = make_float2(v10, v11);
            }
        }
    }
}

// ===================== fp32 tiled GEMM (K=64 fulcon layers) =====================
template <int ACT>
__global__ void __launch_bounds__(256) gemm_nt_kernel(
    const float* __restrict__ A, const float* __restrict__ Wt,
    const float* __restrict__ bias, float* __restrict__ C,
    int Mdim, int Ndim, int Kdim)
{
    __shared__ float As[16][128];
    __shared__ float Ws[16][128];

    const int tid = threadIdx.x;
    const int tx  = tid & 15;
    const int ty  = tid >> 4;
    const int m0  = blockIdx.y * 128;
    const int n0  = blockIdx.x * 128;

    float acc[8][8];
#pragma unroll
    for (int i = 0; i < 8; i++)
#pragma unroll
        for (int j = 0; j < 8; j++) acc[i][j] = 0.0f;

    for (int k0 = 0; k0 < Kdim; k0 += 16) {
#pragma unroll
        for (int it = 0; it < 2; it++) {
            int idx = tid + it * 256;
            int row = idx >> 2;
            int kq  = (idx & 3) * 4;
            float4 v = *reinterpret_cast<const float4*>(
                &A[(size_t)(m0 + row) * Kdim + k0 + kq]);
            As[kq + 0][row] = v.x; As[kq + 1][row] = v.y;
            As[kq + 2][row] = v.z; As[kq + 3][row] = v.w;
        }
#pragma unroll
        for (int it = 0; it < 2; it++) {
            int idx = tid + it * 256;
            int row = idx >> 2;
            int kq  = (idx & 3) * 4;
            float4 v = *reinterpret_cast<const float4*>(
                &Wt[(size_t)(n0 + row) * Kdim + k0 + kq]);
            Ws[kq + 0][row] = v.x; Ws[kq + 1][row] = v.y;
            Ws[kq + 2][row] = v.z; Ws[kq + 3][row] = v.w;
        }
        __syncthreads();

#pragma unroll
        for (int k = 0; k < 16; k++) {
            float ar[8], br[8];
            *reinterpret_cast<float4*>(&ar[0]) = *reinterpret_cast<const float4*>(&As[k][ty * 8]);
            *reinterpret_cast<float4*>(&ar[4]) = *reinterpret_cast<const float4*>(&As[k][ty * 8 + 4]);
            *reinterpret_cast<float4*>(&br[0]) = *reinterpret_cast<const float4*>(&Ws[k][tx * 8]);
            *reinterpret_cast<float4*>(&br[4]) = *reinterpret_cast<const float4*>(&Ws[k][tx * 8 + 4]);
#pragma unroll
            for (int i = 0; i < 8; i++)
#pragma unroll
                for (int j = 0; j < 8; j++)
                    acc[i][j] = fmaf(ar[i], br[j], acc[i][j]);
        }
        __syncthreads();
    }

#pragma unroll
    for (int i = 0; i < 8; i++) {
        int m = m0 + ty * 8 + i;
#pragma unroll
        for (int j = 0; j < 8; j++) {
            int n = n0 + tx * 8 + j;
            float v = acc[i][j] + bias[n];
            if (ACT == ACT_RELU)    v = fmaxf(v, 0.0f);
            if (ACT == ACT_SIGMOID) v = sigm(v);
            C[(size_t)m * Ndim + n] = v;
        }
    }
}

// ===================== mu / logvar projection =====================
__global__ void __launch_bounds__(256) mulv_kernel(
    const float* __restrict__ h2,
    const float* __restrict__ mu_w, const float* __restrict__ lv_w,
    float* __restrict__ mulv)
{
    __shared__ float Hs[64][36];
    __shared__ float Ws_[16][36];

    const int tid = threadIdx.x;
    const int b0  = blockIdx.x * 64;
    const int j0  = blockIdx.y * 16;
    const int kb  = blockIdx.z * 1024;

    const int tj  = tid & 15;
    const int tb4 = (tid >> 4) * 4;

    float a0 = 0.0f, a1 = 0.0f, a2 = 0.0f, a3 = 0.0f;

    for (int kt = 0; kt < 32; kt++) {
        int k0 = kb + kt * 32;
#pragma unroll
        for (int it = 0; it < 2; it++) {
            int c = tid + it * 256;
            int row = c >> 3, coff = (c & 7) * 4;
            *reinterpret_cast<float4*>(&Hs[row][coff]) =
                *reinterpret_cast<const float4*>(&h2[(size_t)(b0 + row) * 4096 + k0 + coff]);
        }
        if (tid < 128) {
            int row = tid >> 3, coff = (tid & 7) * 4;
            int jg = j0 + row;
            const float* wr = (jg < 64) ? (mu_w + (size_t)jg * 4096)
                                        : (lv_w + (size_t)(jg - 64) * 4096);
            *reinterpret_cast<float4*>(&Ws_[row][coff]) =
                *reinterpret_cast<const float4*>(&wr[k0 + coff]);
        }
        __syncthreads();

#pragma unroll
        for (int k = 0; k < 32; k += 4) {
            float4 w  = *reinterpret_cast<const float4*>(&Ws_[tj][k]);
            float4 h0 = *reinterpret_cast<const float4*>(&Hs[tb4 + 0][k]);
            float4 h1v= *reinterpret_cast<const float4*>(&Hs[tb4 + 1][k]);
            float4 h2v= *reinterpret_cast<const float4*>(&Hs[tb4 + 2][k]);
            float4 h3 = *reinterpret_cast<const float4*>(&Hs[tb4 + 3][k]);
            a0 = fmaf(w.x, h0.x, fmaf(w.y, h0.y, fmaf(w.z, h0.z, fmaf(w.w, h0.w, a0))));
            a1 = fmaf(w.x, h1v.x, fmaf(w.y, h1v.y, fmaf(w.z, h1v.z, fmaf(w.w, h1v.w, a1))));
            a2 = fmaf(w.x, h2v.x, fmaf(w.y, h2v.y, fmaf(w.z, h2v.z, fmaf(w.w, h2v.w, a2))));
            a3 = fmaf(w.x, h3.x, fmaf(w.y, h3.y, fmaf(w.z, h3.z, fmaf(w.w, h3.w, a3))));
        }
        __syncthreads();
    }

    atomicAdd(&mulv[(size_t)(b0 + tb4 + 0) * 128 + j0 + tj], a0);
    atomicAdd(&mulv[(size_t)(b0 + tb4 + 1) * 128 + j0 + tj], a1);
    atomicAdd(&mulv[(size_t)(b0 + tb4 + 2) * 128 + j0 + tj], a2);
    atomicAdd(&mulv[(size_t)(b0 + tb4 + 3) * 128 + j0 + tj], a3);
}

// ===================== reparameterization + mu/logvar output =====================
__global__ void z_kernel(const float* __restrict__ mulv, const float* __restrict__ eps,
                         const float* __restrict__ mu_b, const float* __restrict__ lv_b,
                         float* __restrict__ z, float* __restrict__ out)
{
    int idx = blockIdx.x * 256 + threadIdx.x;
    if (idx >= B_DIM * Z_DIM) return;
    int b = idx >> 6, j = idx & 63;
    float mu = mulv[(size_t)b * 128 + j]      + mu_b[j];
    float lv = mulv[(size_t)b * 128 + 64 + j] + lv_b[j];
    z[idx] = mu + expf(0.5f * lv) * eps[idx];
    out[OFF_MU + idx] = mu;
    out[OFF_LV + idx] = lv;
}

// ===================== decoder tail =====================
__global__ void __launch_bounds__(256) tail_kernel(
    const float* __restrict__ am, const float* __restrict__ ac,
    const float* __restrict__ mhw, const float* __restrict__ mhb,
    const float* __restrict__ mow, const float* __restrict__ mob,
    const float* __restrict__ chw, const float* __restrict__ chb,
    const float* __restrict__ cow, const float* __restrict__ cob,
    float* __restrict__ out)
{
    int idx = blockIdx.x * 256 + threadIdx.x;
    if (idx >= B_DIM * M_DIM) return;
    int b = idx >> 12, m = idx & 4095;

    {
        float2 a = *reinterpret_cast<const float2*>(&am[(size_t)b * H_DIM + 2 * m]);
        float a0 = a.x, a1 = a.y;
#pragma unroll
        for (int l = 0; l < L_DIM; l++) {
            float4 w = *reinterpret_cast<const float4*>(&mhw[((size_t)l * M_DIM + m) * 4]);
            float b0v = mhb[l * H_DIM + 2 * m];
            float b1v = mhb[l * H_DIM + 2 * m + 1];
            float n0 = sigm(fmaf(a0, w.x, fmaf(a1, w.y, b0v)));
            float n1 = sigm(fmaf(a0, w.z, fmaf(a1, w.w, b1v)));
            a0 = n0; a1 = n1;
        }
        float2 ow = *reinterpret_cast<const float2*>(&mow[2 * m]);
        out[OFF_XREC + idx] = fmaf(a0, ow.x, fmaf(a1, ow.y, mob[m]));
    }
    {
        float2 a = *reinterpret_cast<const float2*>(&ac[(size_t)b * H_DIM + 2 * m]);
        float a0 = a.x, a1 = a.y;
#pragma unroll
        for (int l = 0; l < L_DIM; l++) {
            float4 w = *reinterpret_cast<const float4*>(&chw[((size_t)l * M_DIM + m) * 4]);
            float b0v = chb[l * H_DIM + 2 * m];
            float b1v = chb[l * H_DIM + 2 * m + 1];
            float n0 = sigm(fmaf(a0, w.x, fmaf(a1, w.y, b0v)));
            float n1 = sigm(fmaf(a0, w.z, fmaf(a1, w.w, b1v)));
            a0 = n0; a1 = n1;
        }
        float2 ow = *reinterpret_cast<const float2*>(&cow[2 * m]);
        out[OFF_LCOV + idx] = fmaf(a0, ow.x, fmaf(a1, ow.y, cob[m]));
    }
}

// ===================== launch =====================
extern "C" void kernel_launch(void* const* d_in, const int* in_sizes, int n_in,
                              void* d_out, int out_size)
{
    const float* x        = (const float*)d_in[0];
    const float* eps      = (const float*)d_in[1];
    const float* enc1_w   = (const float*)d_in[2];
    const float* enc1_b   = (const float*)d_in[3];
    const float* enc2_w   = (const float*)d_in[4];
    const float* enc2_b   = (const float*)d_in[5];
    const float* mu_w     = (const float*)d_in[6];
    const float* mu_b     = (const float*)d_in[7];
    const float* lv_w     = (const float*)d_in[8];
    const float* lv_b     = (const float*)d_in[9];
    const float* m_ful_w  = (const float*)d_in[10];
    const float* m_ful_b  = (const float*)d_in[11];
    const float* m_h_w    = (const float*)d_in[12];
    const float* m_h_b    = (const float*)d_in[13];
    const float* m_out_w  = (const float*)d_in[14];
    const float* m_out_b  = (const float*)d_in[15];
    const float* c_ful_w  = (const float*)d_in[16];
    const float* c_ful_b  = (const float*)d_in[17];
    const float* c_h_w    = (const float*)d_in[18];
    const float* c_h_b    = (const float*)d_in[19];
    const float* c_out_w  = (const float*)d_in[20];
    const float* c_out_b  = (const float*)d_in[21];
    float* out = (float*)d_out;

    __half* h1h; float *h2, *mulv, *z, *am, *ac;
    cudaGetSymbolAddress((void**)&h1h,  g_h1h);
    cudaGetSymbolAddress((void**)&h2,   g_h2);
    cudaGetSymbolAddress((void**)&mulv, g_mulv);
    cudaGetSymbolAddress((void**)&z,    g_z);
    cudaGetSymbolAddress((void**)&am,   g_am);
    cudaGetSymbolAddress((void**)&ac,   g_ac);

    // encoder: fp16 mma tensor cores
    dim3 g1(M_DIM / 128, B_DIM / 128);   // (32, 8)
    gemm_h_kernel<float,  __half, ACT_RELU><<<g1, 256>>>(x,   enc1_w, enc1_b, h1h, M_DIM, M_DIM);
    gemm_h_kernel<__half, float,  ACT_RELU><<<g1, 256>>>(h1h, enc2_w, enc2_b, h2,  M_DIM, M_DIM);

    // mu / logvar projection
    cudaMemsetAsync(mulv, 0, B_DIM * 128 * sizeof(float), 0);
    dim3 g2(B_DIM / 64, 128 / 16, 4);
    mulv_kernel<<<g2, 256>>>(h2, mu_w, lv_w, mulv);

    z_kernel<<<(B_DIM * Z_DIM + 255) / 256, 256>>>(mulv, eps, mu_b, lv_b, z, out);

    // decoder fulcon layers (sigmoid), K=64
    dim3 g3(H_DIM / 128, B_DIM / 128);
    gemm_nt_kernel<ACT_SIGMOID><<<g3, 256>>>(z, m_ful_w, m_ful_b, am, B_DIM, H_DIM, Z_DIM);
    gemm_nt_kernel<ACT_SIGMOID><<<g3, 256>>>(z, c_ful_w, c_ful_b, ac, B_DIM, H_DIM, Z_DIM);

    // decoder tail
    tail_kernel<<<(B_DIM * M_DIM + 255) / 256, 256>>>(
        am, ac, m_h_w, m_h_b, m_out_w, m_out_b,
        c_h_w, c_h_b, c_out_w, c_out_b, out);
}

// round 5
// speedup vs baseline: 3.7819x; 1.0704x over previous
#include <cuda_runtime.h>
#include <cuda_fp16.h>
#include <cstdint>
#include <cstddef>

// Problem dims (fixed)
#define B_DIM 1024
#define M_DIM 4096
#define W_DIM 2
#define L_DIM 2
#define Z_DIM 64
#define H_DIM 8192   // M*W

// Output layout: x_recon [B*M], logcov [B*M], mu [B*Z], logvar [B*Z]
#define OFF_XREC  0
#define OFF_LCOV  (B_DIM * M_DIM)
#define OFF_MU    (2 * B_DIM * M_DIM)
#define OFF_LV    (2 * B_DIM * M_DIM + B_DIM * Z_DIM)

// -------- scratch (no allocations allowed; __device__ globals) --------
__device__ __half g_xh [B_DIM * M_DIM];    // x in fp16
__device__ __half g_w1h[M_DIM * M_DIM];    // enc1_w in fp16
__device__ __half g_w2h[M_DIM * M_DIM];    // enc2_w in fp16
__device__ __half g_h1h[B_DIM * M_DIM];    // encoder layer-1 out (fp16)
__device__ float  g_h2 [B_DIM * M_DIM];    // encoder layer-2 out (fp32)
__device__ float  g_mulv[B_DIM * 128];
__device__ float  g_z[B_DIM * Z_DIM];
__device__ float  g_am[B_DIM * H_DIM];
__device__ float  g_ac[B_DIM * H_DIM];

__device__ __forceinline__ float sigm(float x) { return 1.0f / (1.0f + expf(-x)); }

#define ACT_RELU 1
#define ACT_SIGMOID 2

// ===================== fp32 -> fp16 conversion (8 elems/thread) =====================
__global__ void __launch_bounds__(256) f2h_kernel(
    const float* __restrict__ in, __half* __restrict__ out, int n8)
{
    int i = blockIdx.x * 256 + threadIdx.x;
    if (i >= n8) return;
    const float4* p = reinterpret_cast<const float4*>(in) + 2 * (size_t)i;
    float4 a = p[0], b = p[1];
    __half2 h0 = __floats2half2_rn(a.x, a.y);
    __half2 h1 = __floats2half2_rn(a.z, a.w);
    __half2 h2 = __floats2half2_rn(b.x, b.y);
    __half2 h3 = __floats2half2_rn(b.z, b.w);
    uint4 u;
    u.x = *reinterpret_cast<uint32_t*>(&h0);
    u.y = *reinterpret_cast<uint32_t*>(&h1);
    u.z = *reinterpret_cast<uint32_t*>(&h2);
    u.w = *reinterpret_cast<uint32_t*>(&h3);
    reinterpret_cast<uint4*>(out)[i] = u;
}

// ===================== fp16 cp.async tensor-core GEMM =====================
// C = act(A * W^T + bias); A: [Mrows, K] fp16, Wt: [N, K] fp16 (both K-contig).
// CTA 128x128, BK=32, 4-stage cp.async pipeline, 8 warps (64x32), mma.m16n8k16.

__device__ __forceinline__ uint32_t smem_u32(const void* p) {
    uint32_t a;
    asm("{ .reg .u64 t; cvta.to.shared.u64 t, %1; cvt.u32.u64 %0, t; }" : "=r"(a) : "l"(p));
    return a;
}
__device__ __forceinline__ void ldmx4(uint32_t* r, uint32_t addr) {
    asm volatile("ldmatrix.sync.aligned.m8n8.x4.shared.b16 {%0,%1,%2,%3}, [%4];"
                 : "=r"(r[0]), "=r"(r[1]), "=r"(r[2]), "=r"(r[3]) : "r"(addr));
}
__device__ __forceinline__ void ldmx2(uint32_t* r, uint32_t addr) {
    asm volatile("ldmatrix.sync.aligned.m8n8.x2.shared.b16 {%0,%1}, [%2];"
                 : "=r"(r[0]), "=r"(r[1]) : "r"(addr));
}
__device__ __forceinline__ void mma_f16(float* d, const uint32_t* a, const uint32_t* b) {
    asm volatile(
        "mma.sync.aligned.m16n8k16.row.col.f32.f16.f16.f32 "
        "{%0,%1,%2,%3}, {%4,%5,%6,%7}, {%8,%9}, {%0,%1,%2,%3};\n"
        : "+f"(d[0]), "+f"(d[1]), "+f"(d[2]), "+f"(d[3])
        : "r"(a[0]), "r"(a[1]), "r"(a[2]), "r"(a[3]), "r"(b[0]), "r"(b[1]));
}
__device__ __forceinline__ void cp_async16(uint32_t smem_addr, const void* gptr) {
    asm volatile("cp.async.cg.shared.global [%0], [%1], 16;\n" :: "r"(smem_addr), "l"(gptr));
}
__device__ __forceinline__ void cp_commit() { asm volatile("cp.async.commit_group;\n"); }
template <int N> __device__ __forceinline__ void cp_wait() {
    asm volatile("cp.async.wait_group %0;\n" :: "n"(N));
}

#define HS_ROW   80                  // bytes/row: 64B data (32 halves) + 16B pad
#define HS_TILE  (128 * HS_ROW)      // 10240 B
#define HS_STAGE (2 * HS_TILE)       // 20480 B (A + B)
#define N_STAGES 4
#define SM_GEMM_TOTAL (N_STAGES * HS_STAGE)   // 81920 B dynamic

template <typename OT, int ACT>
__global__ void __launch_bounds__(256, 2) gemm_h16_kernel(
    const __half* __restrict__ A, const __half* __restrict__ Wt,
    const float* __restrict__ bias, OT* __restrict__ C,
    int Ndim, int Kdim)
{
    extern __shared__ __align__(16) uint8_t dsm[];
    __shared__ float sbias[128];

    const int tid  = threadIdx.x;
    const int lane = tid & 31;
    const int warp = tid >> 5;
    const int wm   = (warp & 1) * 64;
    const int wn   = (warp >> 1) * 32;
    const int m0   = blockIdx.y * 128;
    const int n0   = blockIdx.x * 128;
    const uint32_t sb = smem_u32(dsm);

    if (tid < 128) sbias[tid] = bias[n0 + tid];

    // cp.async per-thread mapping: 2 chunks of 16B per tile per stage
    const int r0c = tid >> 2,          k0c = (tid & 3) * 8;          // halves
    const int r1c = (tid + 256) >> 2,  k1c = ((tid + 256) & 3) * 8;
    const uint32_t d0 = (uint32_t)r0c * HS_ROW + (k0c & 31) * 2;
    const uint32_t d1 = (uint32_t)r1c * HS_ROW + (k1c & 31) * 2;

    const __half* Ab = A  + (size_t)m0 * Kdim;
    const __half* Bb = Wt + (size_t)n0 * Kdim;

    const int T = Kdim >> 5;   // BK = 32

    auto issue = [&](int it) {
        uint32_t st = sb + (it & (N_STAGES - 1)) * HS_STAGE;
        const __half* Ap = Ab + it * 32;
        const __half* Bp = Bb + it * 32;
        cp_async16(st + d0,            Ap + (size_t)r0c * Kdim + k0c);
        cp_async16(st + d1,            Ap + (size_t)r1c * Kdim + k1c);
        cp_async16(st + HS_TILE + d0,  Bp + (size_t)r0c * Kdim + k0c);
        cp_async16(st + HS_TILE + d1,  Bp + (size_t)r1c * Kdim + k1c);
        cp_commit();
    };

    // ldmatrix per-lane byte offsets
    const uint32_t a_lm = ((lane & 7) + ((lane >> 3) & 1) * 8) * HS_ROW + ((lane >> 4) & 1) * 16;
    const uint32_t b_lm = (lane & 7) * HS_ROW + ((lane >> 3) & 1) * 16;

    float acc[4][4][4];
#pragma unroll
    for (int i = 0; i < 4; i++)
#pragma unroll
        for (int j = 0; j < 4; j++)
#pragma unroll
            for (int r = 0; r < 4; r++) acc[i][j][r] = 0.0f;

    // prologue: stages 0..N_STAGES-2
#pragma unroll
    for (int i = 0; i < N_STAGES - 1; i++) issue(i);

    for (int it = 0; it < T; ++it) {
        cp_wait<N_STAGES - 2>();
        __syncthreads();

        // keep group count uniform: empty commit when no more tiles
        if (it + N_STAGES - 1 < T) issue(it + N_STAGES - 1);
        else cp_commit();

        const uint32_t sa  = sb + (it & (N_STAGES - 1)) * HS_STAGE;
        const uint32_t sbm = sa + HS_TILE;
#pragma unroll
        for (int kk = 0; kk < 2; kk++) {
            uint32_t af[4][4], bf[4][2];
#pragma unroll
            for (int im = 0; im < 4; im++)
                ldmx4(af[im], sa + (wm + im * 16) * HS_ROW + a_lm + kk * 32);
#pragma unroll
            for (int in_ = 0; in_ < 4; in_++)
                ldmx2(bf[in_], sbm + (wn + in_ * 8) * HS_ROW + b_lm + kk * 32);
#pragma unroll
            for (int im = 0; im < 4; im++)
#pragma unroll
                for (int in_ = 0; in_ < 4; in_++)
                    mma_f16(acc[im][in_], af[im], bf[in_]);
        }
    }

    // epilogue: bias + activation
    const int g = lane >> 2, t = lane & 3;
#pragma unroll
    for (int im = 0; im < 4; im++) {
        int r0 = m0 + wm + im * 16 + g;
#pragma unroll
        for (int in_ = 0; in_ < 4; in_++) {
            int cl = wn + in_ * 8 + t * 2;
            float b0v = sbias[cl], b1v = sbias[cl + 1];
            float v00 = acc[im][in_][0] + b0v;
            float v01 = acc[im][in_][1] + b1v;
            float v10 = acc[im][in_][2] + b0v;
            float v11 = acc[im][in_][3] + b1v;
            if (ACT == ACT_RELU) {
                v00 = fmaxf(v00, 0.0f); v01 = fmaxf(v01, 0.0f);
                v10 = fmaxf(v10, 0.0f); v11 = fmaxf(v11, 0.0f);
            }
            if (ACT == ACT_SIGMOID) {
                v00 = sigm(v00); v01 = sigm(v01);
                v10 = sigm(v10); v11 = sigm(v11);
            }
            int c = n0 + cl;
            if (sizeof(OT) == 2) {
                __half* Ch = reinterpret_cast<__half*>(C);
                __half2 lo = __floats2half2_rn(v00, v01);
                __half2 hi = __floats2half2_rn(v10, v11);
                *reinterpret_cast<__half2*>(&Ch[(size_t)r0 * Ndim + c]) = lo;
                *reinterpret_cast<__half2*>(&Ch[(size_t)(r0 + 8) * Ndim + c]) = hi;
            } else {
                float* Cf = reinterpret_cast<float*>(C);
                *reinterpret_cast<float2*>(&Cf[(size_t)r0 * Ndim + c]) = make_float2(v00, v01);
                *reinterpret_cast<float2*>(&Cf[(size_t)(r0 + 8) * Ndim + c]) = make_float2(v10, v11);
            }
        }
    }
}

// ===================== fp32 tiled GEMM (K=64 fulcon layers) =====================
template <int ACT>
__global__ void __launch_bounds__(256) gemm_nt_kernel(
    const float* __restrict__ A, const float* __restrict__ Wt,
    const float* __restrict__ bias, float* __restrict__ C,
    int Mdim, int Ndim, int Kdim)
{
    __shared__ float As[16][128];
    __shared__ float Ws[16][128];

    const int tid = threadIdx.x;
    const int tx  = tid & 15;
    const int ty  = tid >> 4;
    const int m0  = blockIdx.y * 128;
    const int n0  = blockIdx.x * 128;

    float acc[8][8];
#pragma unroll
    for (int i = 0; i < 8; i++)
#pragma unroll
        for (int j = 0; j < 8; j++) acc[i][j] = 0.0f;

    for (int k0 = 0; k0 < Kdim; k0 += 16) {
#pragma unroll
        for (int it = 0; it < 2; it++) {
            int idx = tid + it * 256;
            int row = idx >> 2;
            int kq  = (idx & 3) * 4;
            float4 v = *reinterpret_cast<const float4*>(
                &A[(size_t)(m0 + row) * Kdim + k0 + kq]);
            As[kq + 0][row] = v.x; As[kq + 1][row] = v.y;
            As[kq + 2][row] = v.z; As[kq + 3][row] = v.w;
        }
#pragma unroll
        for (int it = 0; it < 2; it++) {
            int idx = tid + it * 256;
            int row = idx >> 2;
            int kq  = (idx & 3) * 4;
            float4 v = *reinterpret_cast<const float4*>(
                &Wt[(size_t)(n0 + row) * Kdim + k0 + kq]);
            Ws[kq + 0][row] = v.x; Ws[kq + 1][row] = v.y;
            Ws[kq + 2][row] = v.z; Ws[kq + 3][row] = v.w;
        }
        __syncthreads();

#pragma unroll
        for (int k = 0; k < 16; k++) {
            float ar[8], br[8];
            *reinterpret_cast<float4*>(&ar[0]) = *reinterpret_cast<const float4*>(&As[k][ty * 8]);
            *reinterpret_cast<float4*>(&ar[4]) = *reinterpret_cast<const float4*>(&As[k][ty * 8 + 4]);
            *reinterpret_cast<float4*>(&br[0]) = *reinterpret_cast<const float4*>(&Ws[k][tx * 8]);
            *reinterpret_cast<float4*>(&br[4]) = *reinterpret_cast<const float4*>(&Ws[k][tx * 8 + 4]);
#pragma unroll
            for (int i = 0; i < 8; i++)
#pragma unroll
                for (int j = 0; j < 8; j++)
                    acc[i][j] = fmaf(ar[i], br[j], acc[i][j]);
        }
        __syncthreads();
    }

#pragma unroll
    for (int i = 0; i < 8; i++) {
        int m = m0 + ty * 8 + i;
#pragma unroll
        for (int j = 0; j < 8; j++) {
            int n = n0 + tx * 8 + j;
            float v = acc[i][j] + bias[n];
            if (ACT == ACT_RELU)    v = fmaxf(v, 0.0f);
            if (ACT == ACT_SIGMOID) v = sigm(v);
            C[(size_t)m * Ndim + n] = v;
        }
    }
}

// ===================== mu / logvar projection =====================
__global__ void __launch_bounds__(256) mulv_kernel(
    const float* __restrict__ h2,
    const float* __restrict__ mu_w, const float* __restrict__ lv_w,
    float* __restrict__ mulv)
{
    __shared__ float Hs[64][36];
    __shared__ float Ws_[16][36];

    const int tid = threadIdx.x;
    const int b0  = blockIdx.x * 64;
    const int j0  = blockIdx.y * 16;
    const int kb  = blockIdx.z * 1024;

    const int tj  = tid & 15;
    const int tb4 = (tid >> 4) * 4;

    float a0 = 0.0f, a1 = 0.0f, a2 = 0.0f, a3 = 0.0f;

    for (int kt = 0; kt < 32; kt++) {
        int k0 = kb + kt * 32;
#pragma unroll
        for (int it = 0; it < 2; it++) {
            int c = tid + it * 256;
            int row = c >> 3, coff = (c & 7) * 4;
            *reinterpret_cast<float4*>(&Hs[row][coff]) =
                *reinterpret_cast<const float4*>(&h2[(size_t)(b0 + row) * 4096 + k0 + coff]);
        }
        if (tid < 128) {
            int row = tid >> 3, coff = (tid & 7) * 4;
            int jg = j0 + row;
            const float* wr = (jg < 64) ? (mu_w + (size_t)jg * 4096)
                                        : (lv_w + (size_t)(jg - 64) * 4096);
            *reinterpret_cast<float4*>(&Ws_[row][coff]) =
                *reinterpret_cast<const float4*>(&wr[k0 + coff]);
        }
        __syncthreads();

#pragma unroll
        for (int k = 0; k < 32; k += 4) {
            float4 w  = *reinterpret_cast<const float4*>(&Ws_[tj][k]);
            float4 h0 = *reinterpret_cast<const float4*>(&Hs[tb4 + 0][k]);
            float4 h1v= *reinterpret_cast<const float4*>(&Hs[tb4 + 1][k]);
            float4 h2v= *reinterpret_cast<const float4*>(&Hs[tb4 + 2][k]);
            float4 h3 = *reinterpret_cast<const float4*>(&Hs[tb4 + 3][k]);
            a0 = fmaf(w.x, h0.x, fmaf(w.y, h0.y, fmaf(w.z, h0.z, fmaf(w.w, h0.w, a0))));
            a1 = fmaf(w.x, h1v.x, fmaf(w.y, h1v.y, fmaf(w.z, h1v.z, fmaf(w.w, h1v.w, a1))));
            a2 = fmaf(w.x, h2v.x, fmaf(w.y, h2v.y, fmaf(w.z, h2v.z, fmaf(w.w, h2v.w, a2))));
            a3 = fmaf(w.x, h3.x, fmaf(w.y, h3.y, fmaf(w.z, h3.z, fmaf(w.w, h3.w, a3))));
        }
        __syncthreads();
    }

    atomicAdd(&mulv[(size_t)(b0 + tb4 + 0) * 128 + j0 + tj], a0);
    atomicAdd(&mulv[(size_t)(b0 + tb4 + 1) * 128 + j0 + tj], a1);
    atomicAdd(&mulv[(size_t)(b0 + tb4 + 2) * 128 + j0 + tj], a2);
    atomicAdd(&mulv[(size_t)(b0 + tb4 + 3) * 128 + j0 + tj], a3);
}

// ===================== reparameterization + mu/logvar output =====================
__global__ void z_kernel(const float* __restrict__ mulv, const float* __restrict__ eps,
                         const float* __restrict__ mu_b, const float* __restrict__ lv_b,
                         float* __restrict__ z, float* __restrict__ out)
{
    int idx = blockIdx.x * 256 + threadIdx.x;
    if (idx >= B_DIM * Z_DIM) return;
    int b = idx >> 6, j = idx & 63;
    float mu = mulv[(size_t)b * 128 + j]      + mu_b[j];
    float lv = mulv[(size_t)b * 128 + 64 + j] + lv_b[j];
    z[idx] = mu + expf(0.5f * lv) * eps[idx];
    out[OFF_MU + idx] = mu;
    out[OFF_LV + idx] = lv;
}

// ===================== decoder tail =====================
__global__ void __launch_bounds__(256) tail_kernel(
    const float* __restrict__ am, const float* __restrict__ ac,
    const float* __restrict__ mhw, const float* __restrict__ mhb,
    const float* __restrict__ mow, const float* __restrict__ mob,
    const float* __restrict__ chw, const float* __restrict__ chb,
    const float* __restrict__ cow, const float* __restrict__ cob,
    float* __restrict__ out)
{
    int idx = blockIdx.x * 256 + threadIdx.x;
    if (idx >= B_DIM * M_DIM) return;
    int b = idx >> 12, m = idx & 4095;

    {
        float2 a = *reinterpret_cast<const float2*>(&am[(size_t)b * H_DIM + 2 * m]);
        float a0 = a.x, a1 = a.y;
#pragma unroll
        for (int l = 0; l < L_DIM; l++) {
            float4 w = *reinterpret_cast<const float4*>(&mhw[((size_t)l * M_DIM + m) * 4]);
            float b0v = mhb[l * H_DIM + 2 * m];
            float b1v = mhb[l * H_DIM + 2 * m + 1];
            float n0 = sigm(fmaf(a0, w.x, fmaf(a1, w.y, b0v)));
            float n1 = sigm(fmaf(a0, w.z, fmaf(a1, w.w, b1v)));
            a0 = n0; a1 = n1;
        }
        float2 ow = *reinterpret_cast<const float2*>(&mow[2 * m]);
        out[OFF_XREC + idx] = fmaf(a0, ow.x, fmaf(a1, ow.y, mob[m]));
    }
    {
        float2 a = *reinterpret_cast<const float2*>(&ac[(size_t)b * H_DIM + 2 * m]);
        float a0 = a.x, a1 = a.y;
#pragma unroll
        for (int l = 0; l < L_DIM; l++) {
            float4 w = *reinterpret_cast<const float4*>(&chw[((size_t)l * M_DIM + m) * 4]);
            float b0v = chb[l * H_DIM + 2 * m];
            float b1v = chb[l * H_DIM + 2 * m + 1];
            float n0 = sigm(fmaf(a0, w.x, fmaf(a1, w.y, b0v)));
            float n1 = sigm(fmaf(a0, w.z, fmaf(a1, w.w, b1v)));
            a0 = n0; a1 = n1;
        }
        float2 ow = *reinterpret_cast<const float2*>(&cow[2 * m]);
        out[OFF_LCOV + idx] = fmaf(a0, ow.x, fmaf(a1, ow.y, cob[m]));
    }
}

// ===================== launch =====================
extern "C" void kernel_launch(void* const* d_in, const int* in_sizes, int n_in,
                              void* d_out, int out_size)
{
    const float* x        = (const float*)d_in[0];
    const float* eps      = (const float*)d_in[1];
    const float* enc1_w   = (const float*)d_in[2];
    const float* enc1_b   = (const float*)d_in[3];
    const float* enc2_w   = (const float*)d_in[4];
    const float* enc2_b   = (const float*)d_in[5];
    const float* mu_w     = (const float*)d_in[6];
    const float* mu_b     = (const float*)d_in[7];
    const float* lv_w     = (const float*)d_in[8];
    const float* lv_b     = (const float*)d_in[9];
    const float* m_ful_w  = (const float*)d_in[10];
    const float* m_ful_b  = (const float*)d_in[11];
    const float* m_h_w    = (const float*)d_in[12];
    const float* m_h_b    = (const float*)d_in[13];
    const float* m_out_w  = (const float*)d_in[14];
    const float* m_out_b  = (const float*)d_in[15];
    const float* c_ful_w  = (const float*)d_in[16];
    const float* c_ful_b  = (const float*)d_in[17];
    const float* c_h_w    = (const float*)d_in[18];
    const float* c_h_b    = (const float*)d_in[19];
    const float* c_out_w  = (const float*)d_in[20];
    const float* c_out_b  = (const float*)d_in[21];
    float* out = (float*)d_out;

    __half *xh, *w1h, *w2h, *h1h;
    float *h2, *mulv, *z, *am, *ac;
    cudaGetSymbolAddress((void**)&xh,   g_xh);
    cudaGetSymbolAddress((void**)&w1h,  g_w1h);
    cudaGetSymbolAddress((void**)&w2h,  g_w2h);
    cudaGetSymbolAddress((void**)&h1h,  g_h1h);
    cudaGetSymbolAddress((void**)&h2,   g_h2);
    cudaGetSymbolAddress((void**)&mulv, g_mulv);
    cudaGetSymbolAddress((void**)&z,    g_z);
    cudaGetSymbolAddress((void**)&am,   g_am);
    cudaGetSymbolAddress((void**)&ac,   g_ac);

    cudaFuncSetAttribute(gemm_h16_kernel<__half, ACT_RELU>,
                         cudaFuncAttributeMaxDynamicSharedMemorySize, SM_GEMM_TOTAL);
    cudaFuncSetAttribute(gemm_h16_kernel<float, ACT_RELU>,
                         cudaFuncAttributeMaxDynamicSharedMemorySize, SM_GEMM_TOTAL);

    // ---- prep: fp32 -> fp16 for x, enc1_w, enc2_w ----
    f2h_kernel<<<(B_DIM * M_DIM / 8 + 255) / 256, 256>>>(x,      xh,  B_DIM * M_DIM / 8);
    f2h_kernel<<<(M_DIM * M_DIM / 8 + 255) / 256, 256>>>(enc1_w, w1h, M_DIM * M_DIM / 8);
    f2h_kernel<<<(M_DIM * M_DIM / 8 + 255) / 256, 256>>>(enc2_w, w2h, M_DIM * M_DIM / 8);

    // ---- encoder: fp16 cp.async tensor-core GEMMs ----
    dim3 g1(M_DIM / 128, B_DIM / 128);   // (32, 8)
    gemm_h16_kernel<__half, ACT_RELU><<<g1, 256, SM_GEMM_TOTAL>>>(xh,  w1h, enc1_b, h1h, M_DIM, M_DIM);
    gemm_h16_kernel<float,  ACT_RELU><<<g1, 256, SM_GEMM_TOTAL>>>(h1h, w2h, enc2_b, h2,  M_DIM, M_DIM);

    // ---- mu / logvar projection ----
    cudaMemsetAsync(mulv, 0, B_DIM * 128 * sizeof(float), 0);
    dim3 g2(B_DIM / 64, 128 / 16, 4);
    mulv_kernel<<<g2, 256>>>(h2, mu_w, lv_w, mulv);

    z_kernel<<<(B_DIM * Z_DIM + 255) / 256, 256>>>(mulv, eps, mu_b, lv_b, z, out);

    // ---- decoder fulcon layers (sigmoid), K=64 ----
    dim3 g3(H_DIM / 128, B_DIM / 128);
    gemm_nt_kernel<ACT_SIGMOID><<<g3, 256>>>(z, m_ful_w, m_ful_b, am, B_DIM, H_DIM, Z_DIM);
    gemm_nt_kernel<ACT_SIGMOID><<<g3, 256>>>(z, c_ful_w, c_ful_b, ac, B_DIM, H_DIM, Z_DIM);

    // ---- decoder tail ----
    tail_kernel<<<(B_DIM * M_DIM + 255) / 256, 256>>>(
        am, ac, m_h_w, m_h_b, m_out_w, m_out_b,
        c_h_w, c_h_b, c_out_w, c_out_b, out);
}

// round 6
// speedup vs baseline: 3.7846x; 1.0007x over previous
#include <cuda_runtime.h>
#include <cuda_fp16.h>
#include <cstdint>
#include <cstddef>

// Problem dims (fixed)
#define B_DIM 1024
#define M_DIM 4096
#define W_DIM 2
#define L_DIM 2
#define Z_DIM 64
#define H_DIM 8192   // M*W

// Output layout: x_recon [B*M], logcov [B*M], mu [B*Z], logvar [B*Z]
#define OFF_XREC  0
#define OFF_LCOV  (B_DIM * M_DIM)
#define OFF_MU    (2 * B_DIM * M_DIM)
#define OFF_LV    (2 * B_DIM * M_DIM + B_DIM * Z_DIM)

// -------- scratch (no allocations allowed; __device__ globals) --------
__device__ __half g_xh [B_DIM * M_DIM];    // x in fp16
__device__ __half g_w1h[M_DIM * M_DIM];    // enc1_w in fp16
__device__ __half g_w2h[M_DIM * M_DIM];    // enc2_w in fp16
__device__ __half g_h1h[B_DIM * M_DIM];    // encoder layer-1 out (fp16)
__device__ float  g_h2 [B_DIM * M_DIM];    // encoder layer-2 out (fp32)
__device__ float  g_mulv[B_DIM * 128];
__device__ float  g_z[B_DIM * Z_DIM];
__device__ float  g_am[B_DIM * H_DIM];
__device__ float  g_ac[B_DIM * H_DIM];

__device__ __forceinline__ float sigm(float x) { return 1.0f / (1.0f + expf(-x)); }

#define ACT_RELU 1
#define ACT_SIGMOID 2

// ===================== fp32 -> fp16 conversion (8 elems/thread) =====================
__global__ void __launch_bounds__(256) f2h_kernel(
    const float* __restrict__ in, __half* __restrict__ out, int n8)
{
    int i = blockIdx.x * 256 + threadIdx.x;
    if (i >= n8) return;
    const float4* p = reinterpret_cast<const float4*>(in) + 2 * (size_t)i;
    float4 a = p[0], b = p[1];
    __half2 h0 = __floats2half2_rn(a.x, a.y);
    __half2 h1 = __floats2half2_rn(a.z, a.w);
    __half2 h2 = __floats2half2_rn(b.x, b.y);
    __half2 h3 = __floats2half2_rn(b.z, b.w);
    uint4 u;
    u.x = *reinterpret_cast<uint32_t*>(&h0);
    u.y = *reinterpret_cast<uint32_t*>(&h1);
    u.z = *reinterpret_cast<uint32_t*>(&h2);
    u.w = *reinterpret_cast<uint32_t*>(&h3);
    reinterpret_cast<uint4*>(out)[i] = u;
}

// ===================== fp16 cp.async tensor-core GEMM =====================
// C = act(A * W^T + bias); A: [Mrows, K] fp16, Wt: [N, K] fp16 (both K-contig).
// CTA 128x128, 512 threads (16 warps, warp tile 32x32), BK=32,
// 4-stage cp.async pipeline, mma.m16n8k16 f32 accum.

__device__ __forceinline__ uint32_t smem_u32(const void* p) {
    uint32_t a;
    asm("{ .reg .u64 t; cvta.to.shared.u64 t, %1; cvt.u32.u64 %0, t; }" : "=r"(a) : "l"(p));
    return a;
}
__device__ __forceinline__ void ldmx4(uint32_t* r, uint32_t addr) {
    asm volatile("ldmatrix.sync.aligned.m8n8.x4.shared.b16 {%0,%1,%2,%3}, [%4];"
                 : "=r"(r[0]), "=r"(r[1]), "=r"(r[2]), "=r"(r[3]) : "r"(addr));
}
__device__ __forceinline__ void mma_f16(float* d, const uint32_t* a, const uint32_t* b) {
    asm volatile(
        "mma.sync.aligned.m16n8k16.row.col.f32.f16.f16.f32 "
        "{%0,%1,%2,%3}, {%4,%5,%6,%7}, {%8,%9}, {%0,%1,%2,%3};\n"
        : "+f"(d[0]), "+f"(d[1]), "+f"(d[2]), "+f"(d[3])
        : "r"(a[0]), "r"(a[1]), "r"(a[2]), "r"(a[3]), "r"(b[0]), "r"(b[1]));
}
__device__ __forceinline__ void cp_async16(uint32_t smem_addr, const void* gptr) {
    asm volatile("cp.async.cg.shared.global [%0], [%1], 16;\n" :: "r"(smem_addr), "l"(gptr));
}
__device__ __forceinline__ void cp_commit() { asm volatile("cp.async.commit_group;\n"); }
template <int N> __device__ __forceinline__ void cp_wait() {
    asm volatile("cp.async.wait_group %0;\n" :: "n"(N));
}

#define HS_ROW   80                  // bytes/row: 64B data (32 halves) + 16B pad
#define HS_TILE  (128 * HS_ROW)      // 10240 B
#define HS_STAGE (2 * HS_TILE)       // 20480 B (A + B)
#define N_STAGES 4
#define SM_GEMM_TOTAL (N_STAGES * HS_STAGE)   // 81920 B dynamic

template <typename OT, int ACT>
__global__ void __launch_bounds__(512, 2) gemm_h16_kernel(
    const __half* __restrict__ A, const __half* __restrict__ Wt,
    const float* __restrict__ bias, OT* __restrict__ C,
    int Ndim, int Kdim)
{
    extern __shared__ __align__(16) uint8_t dsm[];
    __shared__ float sbias[128];

    const int tid  = threadIdx.x;
    const int lane = tid & 31;
    const int warp = tid >> 5;               // 0..15
    const int wm   = (warp & 3) * 32;        // warp m offset (4 rows of warps)
    const int wn   = (warp >> 2) * 32;       // warp n offset (4 cols of warps)
    const int m0   = blockIdx.y * 128;
    const int n0   = blockIdx.x * 128;
    const uint32_t sb = smem_u32(dsm);

    if (tid < 128) sbias[tid] = bias[n0 + tid];

    // cp.async per-thread mapping: 1 chunk of 16B per tile per stage (512 chunks)
    const int rC = tid >> 2;                 // 0..127
    const int kC = (tid & 3) * 8;            // halves: 0,8,16,24
    const uint32_t dC = (uint32_t)rC * HS_ROW + kC * 2;

    const __half* Ab = A  + (size_t)m0 * Kdim;
    const __half* Bb = Wt + (size_t)n0 * Kdim;

    const int T = Kdim >> 5;   // BK = 32

    auto issue = [&](int it) {
        uint32_t st = sb + (it & (N_STAGES - 1)) * HS_STAGE;
        cp_async16(st + dC,           Ab + (size_t)rC * Kdim + it * 32 + kC);
        cp_async16(st + HS_TILE + dC, Bb + (size_t)rC * Kdim + it * 32 + kC);
        cp_commit();
    };

    // ldmatrix per-lane byte offsets:
    // A x4: m0=(r0-7,k0-7) m1=(r8-15,k0-7) m2=(r0-7,k8-15) m3=(r8-15,k8-15)
    const uint32_t a_lm = ((lane & 7) + ((lane >> 3) & 1) * 8) * HS_ROW + ((lane >> 4) & 1) * 16;
    // B x4: m0=(n0-7,k0-7) m1=(n0-7,k8-15) m2=(n8-15,k0-7) m3=(n8-15,k8-15)
    const uint32_t b_lm = ((lane & 7) + ((lane >> 4) & 1) * 8) * HS_ROW + ((lane >> 3) & 1) * 16;

    float acc[2][4][4];
#pragma unroll
    for (int i = 0; i < 2; i++)
#pragma unroll
        for (int j = 0; j < 4; j++)
#pragma unroll
            for (int r = 0; r < 4; r++) acc[i][j][r] = 0.0f;

    // prologue: stages 0..N_STAGES-2
#pragma unroll
    for (int i = 0; i < N_STAGES - 1; i++) issue(i);

    for (int it = 0; it < T; ++it) {
        cp_wait<N_STAGES - 2>();
        __syncthreads();

        if (it + N_STAGES - 1 < T) issue(it + N_STAGES - 1);
        else cp_commit();   // keep group count uniform

        const uint32_t sa  = sb + (it & (N_STAGES - 1)) * HS_STAGE;
        const uint32_t sbm = sa + HS_TILE;
#pragma unroll
        for (int kk = 0; kk < 2; kk++) {
            uint32_t af[2][4], bf[2][4];
#pragma unroll
            for (int im = 0; im < 2; im++)
                ldmx4(af[im], sa + (wm + im * 16) * HS_ROW + a_lm + kk * 32);
#pragma unroll
            for (int jn = 0; jn < 2; jn++)
                ldmx4(bf[jn], sbm + (wn + jn * 16) * HS_ROW + b_lm + kk * 32);
#pragma unroll
            for (int im = 0; im < 2; im++)
#pragma unroll
                for (int jn = 0; jn < 2; jn++) {
                    mma_f16(acc[im][2 * jn],     af[im], &bf[jn][0]);
                    mma_f16(acc[im][2 * jn + 1], af[im], &bf[jn][2]);
                }
        }
    }

    // epilogue: bias + activation
    const int g = lane >> 2, t = lane & 3;
#pragma unroll
    for (int im = 0; im < 2; im++) {
        int r0 = m0 + wm + im * 16 + g;
#pragma unroll
        for (int in_ = 0; in_ < 4; in_++) {
            int cl = wn + in_ * 8 + t * 2;
            float b0v = sbias[cl], b1v = sbias[cl + 1];
            float v00 = acc[im][in_][0] + b0v;
            float v01 = acc[im][in_][1] + b1v;
            float v10 = acc[im][in_][2] + b0v;
            float v11 = acc[im][in_][3] + b1v;
            if (ACT == ACT_RELU) {
                v00 = fmaxf(v00, 0.0f); v01 = fmaxf(v01, 0.0f);
                v10 = fmaxf(v10, 0.0f); v11 = fmaxf(v11, 0.0f);
            }
            if (ACT == ACT_SIGMOID) {
                v00 = sigm(v00); v01 = sigm(v01);
                v10 = sigm(v10); v11 = sigm(v11);
            }
            int c = n0 + cl;
            if (sizeof(OT) == 2) {
                __half* Ch = reinterpret_cast<__half*>(C);
                __half2 lo = __floats2half2_rn(v00, v01);
                __half2 hi = __floats2half2_rn(v10, v11);
                *reinterpret_cast<__half2*>(&Ch[(size_t)r0 * Ndim + c]) = lo;
                *reinterpret_cast<__half2*>(&Ch[(size_t)(r0 + 8) * Ndim + c]) = hi;
            } else {
                float* Cf = reinterpret_cast<float*>(C);
                *reinterpret_cast<float2*>(&Cf[(size_t)r0 * Ndim + c]) = make_float2(v00, v01);
                *reinterpret_cast<float2*>(&Cf[(size_t)(r0 + 8) * Ndim + c]) = make_float2(v10, v11);
            }
        }
    }
}

// ===================== fp32 tiled GEMM (K=64 fulcon layers) =====================
template <int ACT>
__global__ void __launch_bounds__(256) gemm_nt_kernel(
    const float* __restrict__ A, const float* __restrict__ Wt,
    const float* __restrict__ bias, float* __restrict__ C,
    int Mdim, int Ndim, int Kdim)
{
    __shared__ float As[16][128];
    __shared__ float Ws[16][128];

    const int tid = threadIdx.x;
    const int tx  = tid & 15;
    const int ty  = tid >> 4;
    const int m0  = blockIdx.y * 128;
    const int n0  = blockIdx.x * 128;

    float acc[8][8];
#pragma unroll
    for (int i = 0; i < 8; i++)
#pragma unroll
        for (int j = 0; j < 8; j++) acc[i][j] = 0.0f;

    for (int k0 = 0; k0 < Kdim; k0 += 16) {
#pragma unroll
        for (int it = 0; it < 2; it++) {
            int idx = tid + it * 256;
            int row = idx >> 2;
            int kq  = (idx & 3) * 4;
            float4 v = *reinterpret_cast<const float4*>(
                &A[(size_t)(m0 + row) * Kdim + k0 + kq]);
            As[kq + 0][row] = v.x; As[kq + 1][row] = v.y;
            As[kq + 2][row] = v.z; As[kq + 3][row] = v.w;
        }
#pragma unroll
        for (int it = 0; it < 2; it++) {
            int idx = tid + it * 256;
            int row = idx >> 2;
            int kq  = (idx & 3) * 4;
            float4 v = *reinterpret_cast<const float4*>(
                &Wt[(size_t)(n0 + row) * Kdim + k0 + kq]);
            Ws[kq + 0][row] = v.x; Ws[kq + 1][row] = v.y;
            Ws[kq + 2][row] = v.z; Ws[kq + 3][row] = v.w;
        }
        __syncthreads();

#pragma unroll
        for (int k = 0; k < 16; k++) {
            float ar[8], br[8];
            *reinterpret_cast<float4*>(&ar[0]) = *reinterpret_cast<const float4*>(&As[k][ty * 8]);
            *reinterpret_cast<float4*>(&ar[4]) = *reinterpret_cast<const float4*>(&As[k][ty * 8 + 4]);
            *reinterpret_cast<float4*>(&br[0]) = *reinterpret_cast<const float4*>(&Ws[k][tx * 8]);
            *reinterpret_cast<float4*>(&br[4]) = *reinterpret_cast<const float4*>(&Ws[k][tx * 8 + 4]);
#pragma unroll
            for (int i = 0; i < 8; i++)
#pragma unroll
                for (int j = 0; j < 8; j++)
                    acc[i][j] = fmaf(ar[i], br[j], acc[i][j]);
        }
        __syncthreads();
    }

#pragma unroll
    for (int i = 0; i < 8; i++) {
        int m = m0 + ty * 8 + i;
#pragma unroll
        for (int j = 0; j < 8; j++) {
            int n = n0 + tx * 8 + j;
            float v = acc[i][j] + bias[n];
            if (ACT == ACT_RELU)    v = fmaxf(v, 0.0f);
            if (ACT == ACT_SIGMOID) v = sigm(v);
            C[(size_t)m * Ndim + n] = v;
        }
    }
}

// ===================== mu / logvar projection =====================
__global__ void __launch_bounds__(256) mulv_kernel(
    const float* __restrict__ h2,
    const float* __restrict__ mu_w, const float* __restrict__ lv_w,
    float* __restrict__ mulv)
{
    __shared__ float Hs[64][36];
    __shared__ float Ws_[16][36];

    const int tid = threadIdx.x;
    const int b0  = blockIdx.x * 64;
    const int j0  = blockIdx.y * 16;
    const int kb  = blockIdx.z * 1024;

    const int tj  = tid & 15;
    const int tb4 = (tid >> 4) * 4;

    float a0 = 0.0f, a1 = 0.0f, a2 = 0.0f, a3 = 0.0f;

    for (int kt = 0; kt < 32; kt++) {
        int k0 = kb + kt * 32;
#pragma unroll
        for (int it = 0; it < 2; it++) {
            int c = tid + it * 256;
            int row = c >> 3, coff = (c & 7) * 4;
            *reinterpret_cast<float4*>(&Hs[row][coff]) =
                *reinterpret_cast<const float4*>(&h2[(size_t)(b0 + row) * 4096 + k0 + coff]);
        }
        if (tid < 128) {
            int row = tid >> 3, coff = (tid & 7) * 4;
            int jg = j0 + row;
            const float* wr = (jg < 64) ? (mu_w + (size_t)jg * 4096)
                                        : (lv_w + (size_t)(jg - 64) * 4096);
            *reinterpret_cast<float4*>(&Ws_[row][coff]) =
                *reinterpret_cast<const float4*>(&wr[k0 + coff]);
        }
        __syncthreads();

#pragma unroll
        for (int k = 0; k < 32; k += 4) {
            float4 w  = *reinterpret_cast<const float4*>(&Ws_[tj][k]);
            float4 h0 = *reinterpret_cast<const float4*>(&Hs[tb4 + 0][k]);
            float4 h1v= *reinterpret_cast<const float4*>(&Hs[tb4 + 1][k]);
            float4 h2v= *reinterpret_cast<const float4*>(&Hs[tb4 + 2][k]);
            float4 h3 = *reinterpret_cast<const float4*>(&Hs[tb4 + 3][k]);
            a0 = fmaf(w.x, h0.x, fmaf(w.y, h0.y, fmaf(w.z, h0.z, fmaf(w.w, h0.w, a0))));
            a1 = fmaf(w.x, h1v.x, fmaf(w.y, h1v.y, fmaf(w.z, h1v.z, fmaf(w.w, h1v.w, a1))));
            a2 = fmaf(w.x, h2v.x, fmaf(w.y, h2v.y, fmaf(w.z, h2v.z, fmaf(w.w, h2v.w, a2))));
            a3 = fmaf(w.x, h3.x, fmaf(w.y, h3.y, fmaf(w.z, h3.z, fmaf(w.w, h3.w, a3))));
        }
        __syncthreads();
    }

    atomicAdd(&mulv[(size_t)(b0 + tb4 + 0) * 128 + j0 + tj], a0);
    atomicAdd(&mulv[(size_t)(b0 + tb4 + 1) * 128 + j0 + tj], a1);
    atomicAdd(&mulv[(size_t)(b0 + tb4 + 2) * 128 + j0 + tj], a2);
    atomicAdd(&mulv[(size_t)(b0 + tb4 + 3) * 128 + j0 + tj], a3);
}

// ===================== reparameterization + mu/logvar output =====================
__global__ void z_kernel(const float* __restrict__ mulv, const float* __restrict__ eps,
                         const float* __restrict__ mu_b, const float* __restrict__ lv_b,
                         float* __restrict__ z, float* __restrict__ out)
{
    int idx = blockIdx.x * 256 + threadIdx.x;
    if (idx >= B_DIM * Z_DIM) return;
    int b = idx >> 6, j = idx & 63;
    float mu = mulv[(size_t)b * 128 + j]      + mu_b[j];
    float lv = mulv[(size_t)b * 128 + 64 + j] + lv_b[j];
    z[idx] = mu + expf(0.5f * lv) * eps[idx];
    out[OFF_MU + idx] = mu;
    out[OFF_LV + idx] = lv;
}

// ===================== decoder tail =====================
__global__ void __launch_bounds__(256) tail_kernel(
    const float* __restrict__ am, const float* __restrict__ ac,
    const float* __restrict__ mhw, const float* __restrict__ mhb,
    const float* __restrict__ mow, const float* __restrict__ mob,
    const float* __restrict__ chw, const float* __restrict__ chb,
    const float* __restrict__ cow, const float* __restrict__ cob,
    float* __restrict__ out)
{
    int idx = blockIdx.x * 256 + threadIdx.x;
    if (idx >= B_DIM * M_DIM) return;
    int b = idx >> 12, m = idx & 4095;

    {
        float2 a = *reinterpret_cast<const float2*>(&am[(size_t)b * H_DIM + 2 * m]);
        float a0 = a.x, a1 = a.y;
#pragma unroll
        for (int l = 0; l < L_DIM; l++) {
            float4 w = *reinterpret_cast<const float4*>(&mhw[((size_t)l * M_DIM + m) * 4]);
            float b0v = mhb[l * H_DIM + 2 * m];
            float b1v = mhb[l * H_DIM + 2 * m + 1];
            float n0 = sigm(fmaf(a0, w.x, fmaf(a1, w.y, b0v)));
            float n1 = sigm(fmaf(a0, w.z, fmaf(a1, w.w, b1v)));
            a0 = n0; a1 = n1;
        }
        float2 ow = *reinterpret_cast<const float2*>(&mow[2 * m]);
        out[OFF_XREC + idx] = fmaf(a0, ow.x, fmaf(a1, ow.y, mob[m]));
    }
    {
        float2 a = *reinterpret_cast<const float2*>(&ac[(size_t)b * H_DIM + 2 * m]);
        float a0 = a.x, a1 = a.y;
#pragma unroll
        for (int l = 0; l < L_DIM; l++) {
            float4 w = *reinterpret_cast<const float4*>(&chw[((size_t)l * M_DIM + m) * 4]);
            float b0v = chb[l * H_DIM + 2 * m];
            float b1v = chb[l * H_DIM + 2 * m + 1];
            float n0 = sigm(fmaf(a0, w.x, fmaf(a1, w.y, b0v)));
            float n1 = sigm(fmaf(a0, w.z, fmaf(a1, w.w, b1v)));
            a0 = n0; a1 = n1;
        }
        float2 ow = *reinterpret_cast<const float2*>(&cow[2 * m]);
        out[OFF_LCOV + idx] = fmaf(a0, ow.x, fmaf(a1, ow.y, cob[m]));
    }
}

// ===================== launch =====================
extern "C" void kernel_launch(void* const* d_in, const int* in_sizes, int n_in,
                              void* d_out, int out_size)
{
    const float* x        = (const float*)d_in[0];
    const float* eps      = (const float*)d_in[1];
    const float* enc1_w   = (const float*)d_in[2];
    const float* enc1_b   = (const float*)d_in[3];
    const float* enc2_w   = (const float*)d_in[4];
    const float* enc2_b   = (const float*)d_in[5];
    const float* mu_w     = (const float*)d_in[6];
    const float* mu_b     = (const float*)d_in[7];
    const float* lv_w     = (const float*)d_in[8];
    const float* lv_b     = (const float*)d_in[9];
    const float* m_ful_w  = (const float*)d_in[10];
    const float* m_ful_b  = (const float*)d_in[11];
    const float* m_h_w    = (const float*)d_in[12];
    const float* m_h_b    = (const float*)d_in[13];
    const float* m_out_w  = (const float*)d_in[14];
    const float* m_out_b  = (const float*)d_in[15];
    const float* c_ful_w  = (const float*)d_in[16];
    const float* c_ful_b  = (const float*)d_in[17];
    const float* c_h_w    = (const float*)d_in[18];
    const float* c_h_b    = (const float*)d_in[19];
    const float* c_out_w  = (const float*)d_in[20];
    const float* c_out_b  = (const float*)d_in[21];
    float* out = (float*)d_out;

    __half *xh, *w1h, *w2h, *h1h;
    float *h2, *mulv, *z, *am, *ac;
    cudaGetSymbolAddress((void**)&xh,   g_xh);
    cudaGetSymbolAddress((void**)&w1h,  g_w1h);
    cudaGetSymbolAddress((void**)&w2h,  g_w2h);
    cudaGetSymbolAddress((void**)&h1h,  g_h1h);
    cudaGetSymbolAddress((void**)&h2,   g_h2);
    cudaGetSymbolAddress((void**)&mulv, g_mulv);
    cudaGetSymbolAddress((void**)&z,    g_z);
    cudaGetSymbolAddress((void**)&am,   g_am);
    cudaGetSymbolAddress((void**)&ac,   g_ac);

    cudaFuncSetAttribute(gemm_h16_kernel<__half, ACT_RELU>,
                         cudaFuncAttributeMaxDynamicSharedMemorySize, SM_GEMM_TOTAL);
    cudaFuncSetAttribute(gemm_h16_kernel<float, ACT_RELU>,
                         cudaFuncAttributeMaxDynamicSharedMemorySize, SM_GEMM_TOTAL);

    // ---- prep: fp32 -> fp16 for x, enc1_w, enc2_w ----
    f2h_kernel<<<(B_DIM * M_DIM / 8 + 255) / 256, 256>>>(x,      xh,  B_DIM * M_DIM / 8);
    f2h_kernel<<<(M_DIM * M_DIM / 8 + 255) / 256, 256>>>(enc1_w, w1h, M_DIM * M_DIM / 8);
    f2h_kernel<<<(M_DIM * M_DIM / 8 + 255) / 256, 256>>>(enc2_w, w2h, M_DIM * M_DIM / 8);

    // ---- encoder: fp16 cp.async tensor-core GEMMs ----
    dim3 g1(M_DIM / 128, B_DIM / 128);   // (32, 8)
    gemm_h16_kernel<__half, ACT_RELU><<<g1, 512, SM_GEMM_TOTAL>>>(xh,  w1h, enc1_b, h1h, M_DIM, M_DIM);
    gemm_h16_kernel<float,  ACT_RELU><<<g1, 512, SM_GEMM_TOTAL>>>(h1h, w2h, enc2_b, h2,  M_DIM, M_DIM);

    // ---- mu / logvar projection ----
    cudaMemsetAsync(mulv, 0, B_DIM * 128 * sizeof(float), 0);
    dim3 g2(B_DIM / 64, 128 / 16, 4);
    mulv_kernel<<<g2, 256>>>(h2, mu_w, lv_w, mulv);

    z_kernel<<<(B_DIM * Z_DIM + 255) / 256, 256>>>(mulv, eps, mu_b, lv_b, z, out);

    // ---- decoder fulcon layers (sigmoid), K=64 ----
    dim3 g3(H_DIM / 128, B_DIM / 128);
    gemm_nt_kernel<ACT_SIGMOID><<<g3, 256>>>(z, m_ful_w, m_ful_b, am, B_DIM, H_DIM, Z_DIM);
    gemm_nt_kernel<ACT_SIGMOID><<<g3, 256>>>(z, c_ful_w, c_ful_b, ac, B_DIM, H_DIM, Z_DIM);

    // ---- decoder tail ----
    tail_kernel<<<(B_DIM * M_DIM + 255) / 256, 256>>>(
        am, ac, m_h_w, m_h_b, m_out_w, m_out_b,
        c_h_w, c_h_b, c_out_w, c_out_b, out);
}

// round 7
// speedup vs baseline: 4.3686x; 1.1543x over previous
#include <cuda_runtime.h>
#include <cuda_fp16.h>
#include <cstdint>
#include <cstddef>

// Problem dims (fixed)
#define B_DIM 1024
#define M_DIM 4096
#define W_DIM 2
#define L_DIM 2
#define Z_DIM 64
#define H_DIM 8192   // M*W

// Output layout: x_recon [B*M], logcov [B*M], mu [B*Z], logvar [B*Z]
#define OFF_XREC  0
#define OFF_LCOV  (B_DIM * M_DIM)
#define OFF_MU    (2 * B_DIM * M_DIM)
#define OFF_LV    (2 * B_DIM * M_DIM + B_DIM * Z_DIM)

// -------- scratch (no allocations allowed; __device__ globals) --------
__device__ __half g_xh [B_DIM * M_DIM];    // x in fp16
__device__ __half g_w1h[M_DIM * M_DIM];    // enc1_w in fp16
__device__ __half g_w2h[M_DIM * M_DIM];    // enc2_w in fp16
__device__ __half g_h1h[B_DIM * M_DIM];    // encoder layer-1 out (fp16)
__device__ float  g_h2 [B_DIM * M_DIM];    // encoder layer-2 out (fp32)
__device__ float  g_mulv[B_DIM * 128];
__device__ float  g_z[B_DIM * Z_DIM];

__device__ __forceinline__ float sigm(float x) { return 1.0f / (1.0f + expf(-x)); }

#define ACT_RELU 1

// ===================== merged fp32 -> fp16 conversion =====================
// Converts x (B*M), enc1_w (M*M), enc2_w (M*M) in one launch; 8 elems/thread.
#define NX8 (B_DIM * M_DIM / 8)
#define NW8 (M_DIM * M_DIM / 8)
__global__ void __launch_bounds__(256) f2h3_kernel(
    const float* __restrict__ x, const float* __restrict__ w1, const float* __restrict__ w2,
    __half* __restrict__ xh, __half* __restrict__ w1h, __half* __restrict__ w2h)
{
    int i = blockIdx.x * 256 + threadIdx.x;
    const float* in; __half* out; int j;
    if (i < NX8)            { in = x;  out = xh;  j = i; }
    else if (i < NX8 + NW8) { in = w1; out = w1h; j = i - NX8; }
    else if (i < NX8 + 2 * NW8) { in = w2; out = w2h; j = i - NX8 - NW8; }
    else return;
    const float4* p = reinterpret_cast<const float4*>(in) + 2 * (size_t)j;
    float4 a = p[0], b = p[1];
    __half2 h0 = __floats2half2_rn(a.x, a.y);
    __half2 h1 = __floats2half2_rn(a.z, a.w);
    __half2 h2 = __floats2half2_rn(b.x, b.y);
    __half2 h3 = __floats2half2_rn(b.z, b.w);
    uint4 u;
    u.x = *reinterpret_cast<uint32_t*>(&h0);
    u.y = *reinterpret_cast<uint32_t*>(&h1);
    u.z = *reinterpret_cast<uint32_t*>(&h2);
    u.w = *reinterpret_cast<uint32_t*>(&h3);
    reinterpret_cast<uint4*>(out)[j] = u;
}

// ===================== fp16 cp.async tensor-core GEMM (unchanged, at mma.sync ceiling) =====
__device__ __forceinline__ uint32_t smem_u32(const void* p) {
    uint32_t a;
    asm("{ .reg .u64 t; cvta.to.shared.u64 t, %1; cvt.u32.u64 %0, t; }" : "=r"(a) : "l"(p));
    return a;
}
__device__ __forceinline__ void ldmx4(uint32_t* r, uint32_t addr) {
    asm volatile("ldmatrix.sync.aligned.m8n8.x4.shared.b16 {%0,%1,%2,%3}, [%4];"
                 : "=r"(r[0]), "=r"(r[1]), "=r"(r[2]), "=r"(r[3]) : "r"(addr));
}
__device__ __forceinline__ void mma_f16(float* d, const uint32_t* a, const uint32_t* b) {
    asm volatile(
        "mma.sync.aligned.m16n8k16.row.col.f32.f16.f16.f32 "
        "{%0,%1,%2,%3}, {%4,%5,%6,%7}, {%8,%9}, {%0,%1,%2,%3};\n"
        : "+f"(d[0]), "+f"(d[1]), "+f"(d[2]), "+f"(d[3])
        : "r"(a[0]), "r"(a[1]), "r"(a[2]), "r"(a[3]), "r"(b[0]), "r"(b[1]));
}
__device__ __forceinline__ void cp_async16(uint32_t smem_addr, const void* gptr) {
    asm volatile("cp.async.cg.shared.global [%0], [%1], 16;\n" :: "r"(smem_addr), "l"(gptr));
}
__device__ __forceinline__ void cp_commit() { asm volatile("cp.async.commit_group;\n"); }
template <int N> __device__ __forceinline__ void cp_wait() {
    asm volatile("cp.async.wait_group %0;\n" :: "n"(N));
}

#define HS_ROW   80
#define HS_TILE  (128 * HS_ROW)
#define HS_STAGE (2 * HS_TILE)
#define N_STAGES 4
#define SM_GEMM_TOTAL (N_STAGES * HS_STAGE)   // 81920 B dynamic

template <typename OT, int ACT>
__global__ void __launch_bounds__(512, 2) gemm_h16_kernel(
    const __half* __restrict__ A, const __half* __restrict__ Wt,
    const float* __restrict__ bias, OT* __restrict__ C,
    int Ndim, int Kdim)
{
    extern __shared__ __align__(16) uint8_t dsm[];
    __shared__ float sbias[128];

    const int tid  = threadIdx.x;
    const int lane = tid & 31;
    const int warp = tid >> 5;
    const int wm   = (warp & 3) * 32;
    const int wn   = (warp >> 2) * 32;
    const int m0   = blockIdx.y * 128;
    const int n0   = blockIdx.x * 128;
    const uint32_t sb = smem_u32(dsm);

    if (tid < 128) sbias[tid] = bias[n0 + tid];

    const int rC = tid >> 2;
    const int kC = (tid & 3) * 8;
    const uint32_t dC = (uint32_t)rC * HS_ROW + kC * 2;

    const __half* Ab = A  + (size_t)m0 * Kdim;
    const __half* Bb = Wt + (size_t)n0 * Kdim;

    const int T = Kdim >> 5;

    auto issue = [&](int it) {
        uint32_t st = sb + (it & (N_STAGES - 1)) * HS_STAGE;
        cp_async16(st + dC,           Ab + (size_t)rC * Kdim + it * 32 + kC);
        cp_async16(st + HS_TILE + dC, Bb + (size_t)rC * Kdim + it * 32 + kC);
        cp_commit();
    };

    const uint32_t a_lm = ((lane & 7) + ((lane >> 3) & 1) * 8) * HS_ROW + ((lane >> 4) & 1) * 16;
    const uint32_t b_lm = ((lane & 7) + ((lane >> 4) & 1) * 8) * HS_ROW + ((lane >> 3) & 1) * 16;

    float acc[2][4][4];
#pragma unroll
    for (int i = 0; i < 2; i++)
#pragma unroll
        for (int j = 0; j < 4; j++)
#pragma unroll
            for (int r = 0; r < 4; r++) acc[i][j][r] = 0.0f;

#pragma unroll
    for (int i = 0; i < N_STAGES - 1; i++) issue(i);

    for (int it = 0; it < T; ++it) {
        cp_wait<N_STAGES - 2>();
        __syncthreads();

        if (it + N_STAGES - 1 < T) issue(it + N_STAGES - 1);
        else cp_commit();

        const uint32_t sa  = sb + (it & (N_STAGES - 1)) * HS_STAGE;
        const uint32_t sbm = sa + HS_TILE;
#pragma unroll
        for (int kk = 0; kk < 2; kk++) {
            uint32_t af[2][4], bf[2][4];
#pragma unroll
            for (int im = 0; im < 2; im++)
                ldmx4(af[im], sa + (wm + im * 16) * HS_ROW + a_lm + kk * 32);
#pragma unroll
            for (int jn = 0; jn < 2; jn++)
                ldmx4(bf[jn], sbm + (wn + jn * 16) * HS_ROW + b_lm + kk * 32);
#pragma unroll
            for (int im = 0; im < 2; im++)
#pragma unroll
                for (int jn = 0; jn < 2; jn++) {
                    mma_f16(acc[im][2 * jn],     af[im], &bf[jn][0]);
                    mma_f16(acc[im][2 * jn + 1], af[im], &bf[jn][2]);
                }
        }
    }

    const int g = lane >> 2, t = lane & 3;
#pragma unroll
    for (int im = 0; im < 2; im++) {
        int r0 = m0 + wm + im * 16 + g;
#pragma unroll
        for (int in_ = 0; in_ < 4; in_++) {
            int cl = wn + in_ * 8 + t * 2;
            float b0v = sbias[cl], b1v = sbias[cl + 1];
            float v00 = acc[im][in_][0] + b0v;
            float v01 = acc[im][in_][1] + b1v;
            float v10 = acc[im][in_][2] + b0v;
            float v11 = acc[im][in_][3] + b1v;
            if (ACT == ACT_RELU) {
                v00 = fmaxf(v00, 0.0f); v01 = fmaxf(v01, 0.0f);
                v10 = fmaxf(v10, 0.0f); v11 = fmaxf(v11, 0.0f);
            }
            int c = n0 + cl;
            if (sizeof(OT) == 2) {
                __half* Ch = reinterpret_cast<__half*>(C);
                __half2 lo = __floats2half2_rn(v00, v01);
                __half2 hi = __floats2half2_rn(v10, v11);
                *reinterpret_cast<__half2*>(&Ch[(size_t)r0 * Ndim + c]) = lo;
                *reinterpret_cast<__half2*>(&Ch[(size_t)(r0 + 8) * Ndim + c]) = hi;
            } else {
                float* Cf = reinterpret_cast<float*>(C);
                *reinterpret_cast<float2*>(&Cf[(size_t)r0 * Ndim + c]) = make_float2(v00, v01);
                *reinterpret_cast<float2*>(&Cf[(size_t)(r0 + 8) * Ndim + c]) = make_float2(v10, v11);
            }
        }
    }
}

// ===================== mu / logvar projection (wide-j, k-split) =====================
// grid (B/64, 4096/512); block 256. Tile: 64 b x 128 j, K-chunk 512.
// Each thread: 4 j (jq*4..) x 8 b (bq*8..). mulv zeroed beforehand; bias in z_kernel.
__global__ void __launch_bounds__(256) mulv_kernel(
    const float* __restrict__ h2,
    const float* __restrict__ mu_w, const float* __restrict__ lv_w,
    float* __restrict__ mulv)
{
    __shared__ float Hs[64][36];        // [b][k] row-major
    __shared__ float Wt_t[32][132];     // [k][j] transposed

    const int tid = threadIdx.x;
    const int b0  = blockIdx.x * 64;
    const int kb  = blockIdx.y * 512;
    const int jq  = tid & 31;           // j group (4 outputs)
    const int bq  = tid >> 5;           // b group (8 rows)

    float acc[8][4];
#pragma unroll
    for (int r = 0; r < 8; r++)
#pragma unroll
        for (int q = 0; q < 4; q++) acc[r][q] = 0.0f;

    for (int kt = 0; kt < 16; kt++) {   // 16 sub-chunks of 32
        int k0 = kb + kt * 32;
        // Hs: 64 x 32 = 512 float4, 2/thread
#pragma unroll
        for (int it = 0; it < 2; it++) {
            int c = tid + it * 256;
            int row = c >> 3, coff = (c & 7) * 4;
            *reinterpret_cast<float4*>(&Hs[row][coff]) =
                *reinterpret_cast<const float4*>(&h2[(size_t)(b0 + row) * 4096 + k0 + coff]);
        }
        // Wt_t: 128 j x 32 k, transposed store; 1024 float4 reads, 4/thread
#pragma unroll
        for (int it = 0; it < 4; it++) {
            int c = tid + it * 256;
            int j = c >> 3, kq = (c & 7) * 4;
            const float* wr = (j < 64) ? (mu_w + (size_t)j * 4096)
                                       : (lv_w + (size_t)(j - 64) * 4096);
            float4 v = *reinterpret_cast<const float4*>(&wr[k0 + kq]);
            Wt_t[kq + 0][j] = v.x; Wt_t[kq + 1][j] = v.y;
            Wt_t[kq + 2][j] = v.z; Wt_t[kq + 3][j] = v.w;
        }
        __syncthreads();

#pragma unroll 4
        for (int k = 0; k < 32; k++) {
            float4 w = *reinterpret_cast<const float4*>(&Wt_t[k][jq * 4]);
#pragma unroll
            for (int r = 0; r < 8; r++) {
                float h = Hs[bq * 8 + r][k];
                acc[r][0] = fmaf(h, w.x, acc[r][0]);
                acc[r][1] = fmaf(h, w.y, acc[r][1]);
                acc[r][2] = fmaf(h, w.z, acc[r][2]);
                acc[r][3] = fmaf(h, w.w, acc[r][3]);
            }
        }
        __syncthreads();
    }

#pragma unroll
    for (int r = 0; r < 8; r++)
#pragma unroll
        for (int q = 0; q < 4; q++)
            atomicAdd(&mulv[(size_t)(b0 + bq * 8 + r) * 128 + jq * 4 + q], acc[r][q]);
}

// ===================== reparameterization + mu/logvar output =====================
__global__ void z_kernel(const float* __restrict__ mulv, const float* __restrict__ eps,
                         const float* __restrict__ mu_b, const float* __restrict__ lv_b,
                         float* __restrict__ z, float* __restrict__ out)
{
    int idx = blockIdx.x * 256 + threadIdx.x;
    if (idx >= B_DIM * Z_DIM) return;
    int b = idx >> 6, j = idx & 63;
    float mu = mulv[(size_t)b * 128 + j]      + mu_b[j];
    float lv = mulv[(size_t)b * 128 + 64 + j] + lv_b[j];
    z[idx] = mu + expf(0.5f * lv) * eps[idx];
    out[OFF_MU + idx] = mu;
    out[OFF_LV + idx] = lv;
}

// ===================== fused decoder: fulcon GEMM + block-diag layers + output =======
// grid (H/128, B/128, 2); block 256. One branch per blockIdx.z.
// smem: Zs_t [64][132] (k-major z tile), Ws_t [64][132] (k-major ful_w tile).
// After GEMM, Zs_t region is reused as Os [128 b][64 m] output staging.
#define DEC_SMEM (2 * 64 * 132 * 4)    // 67584 B

__global__ void __launch_bounds__(256) decoder_kernel(
    const float* __restrict__ z,
    const float* __restrict__ m_ful_w, const float* __restrict__ m_ful_b,
    const float* __restrict__ m_h_w,   const float* __restrict__ m_h_b,
    const float* __restrict__ m_out_w, const float* __restrict__ m_out_b,
    const float* __restrict__ c_ful_w, const float* __restrict__ c_ful_b,
    const float* __restrict__ c_h_w,   const float* __restrict__ c_h_b,
    const float* __restrict__ c_out_w, const float* __restrict__ c_out_b,
    float* __restrict__ out)
{
    extern __shared__ float ds[];
    float* Zs = ds;               // [64 k][132]
    float* Ws = ds + 64 * 132;    // [64 k][132]
    __shared__ float sfb[128];

    const bool mean = (blockIdx.z == 0);
    const float* fw = mean ? m_ful_w : c_ful_w;
    const float* fb = mean ? m_ful_b : c_ful_b;
    const float* hw = mean ? m_h_w   : c_h_w;
    const float* hb = mean ? m_h_b   : c_h_b;
    const float* ow = mean ? m_out_w : c_out_w;
    const float* ob = mean ? m_out_b : c_out_b;
    const int out_off = mean ? OFF_XREC : OFF_LCOV;

    const int tid = threadIdx.x;
    const int tx  = tid & 15;     // h direction (8 cols)
    const int ty  = tid >> 4;     // b direction (8 rows)
    const int n0  = blockIdx.x * 128;   // h base
    const int b0  = blockIdx.y * 128;   // batch base

    // load z tile transposed: z[b0+row][kq] -> Zs[kq][row]
#pragma unroll
    for (int it = 0; it < 8; it++) {
        int idx = tid + it * 256;       // 0..2047
        int row = idx >> 4, kq = (idx & 15) * 4;
        float4 v = *reinterpret_cast<const float4*>(&z[(size_t)(b0 + row) * 64 + kq]);
        Zs[(kq + 0) * 132 + row] = v.x; Zs[(kq + 1) * 132 + row] = v.y;
        Zs[(kq + 2) * 132 + row] = v.z; Zs[(kq + 3) * 132 + row] = v.w;
    }
    // load ful_w tile transposed: fw[n0+row][kq] -> Ws[kq][row]
#pragma unroll
    for (int it = 0; it < 8; it++) {
        int idx = tid + it * 256;
        int row = idx >> 4, kq = (idx & 15) * 4;
        float4 v = *reinterpret_cast<const float4*>(&fw[(size_t)(n0 + row) * 64 + kq]);
        Ws[(kq + 0) * 132 + row] = v.x; Ws[(kq + 1) * 132 + row] = v.y;
        Ws[(kq + 2) * 132 + row] = v.z; Ws[(kq + 3) * 132 + row] = v.w;
    }
    if (tid < 128) sfb[tid] = fb[n0 + tid];
    __syncthreads();

    // fulcon GEMM: acc[b-sub][h-sub], K = 64
    float acc[8][8];
#pragma unroll
    for (int i = 0; i < 8; i++)
#pragma unroll
        for (int j = 0; j < 8; j++) acc[i][j] = 0.0f;

#pragma unroll 4
    for (int k = 0; k < 64; k++) {
        float ar[8], br[8];
        *reinterpret_cast<float4*>(&ar[0]) = *reinterpret_cast<const float4*>(&Zs[k * 132 + ty * 8]);
        *reinterpret_cast<float4*>(&ar[4]) = *reinterpret_cast<const float4*>(&Zs[k * 132 + ty * 8 + 4]);
        *reinterpret_cast<float4*>(&br[0]) = *reinterpret_cast<const float4*>(&Ws[k * 132 + tx * 8]);
        *reinterpret_cast<float4*>(&br[4]) = *reinterpret_cast<const float4*>(&Ws[k * 132 + tx * 8 + 4]);
#pragma unroll
        for (int i = 0; i < 8; i++)
#pragma unroll
            for (int j = 0; j < 8; j++)
                acc[i][j] = fmaf(ar[i], br[j], acc[i][j]);
    }
    // bias + sigmoid
#pragma unroll
    for (int i = 0; i < 8; i++)
#pragma unroll
        for (int j = 0; j < 8; j++)
            acc[i][j] = sigm(acc[i][j] + sfb[tx * 8 + j]);

    __syncthreads();   // before reusing Zs region as Os
    float* Os = ds;    // [128 b][64 m]

    // tail: 4 m-pairs per thread (h cols tx*8 + {0,1},{2,3},{4,5},{6,7})
#pragma unroll
    for (int jj = 0; jj < 4; jj++) {
        int m = (n0 >> 1) + tx * 4 + jj;    // global m
        float4 w0 = *reinterpret_cast<const float4*>(&hw[(size_t)m * 4]);
        float4 w1 = *reinterpret_cast<const float4*>(&hw[((size_t)M_DIM + m) * 4]);
        float b00 = hb[2 * m],          b01 = hb[2 * m + 1];
        float b10 = hb[H_DIM + 2 * m],  b11 = hb[H_DIM + 2 * m + 1];
        float2 owv = *reinterpret_cast<const float2*>(&ow[2 * m]);
        float obv = ob[m];
#pragma unroll
        for (int i = 0; i < 8; i++) {
            float a0 = acc[i][2 * jj], a1 = acc[i][2 * jj + 1];
            float t0 = sigm(fmaf(a0, w0.x, fmaf(a1, w0.y, b00)));
            float t1 = sigm(fmaf(a0, w0.z, fmaf(a1, w0.w, b01)));
            a0 = sigm(fmaf(t0, w1.x, fmaf(t1, w1.y, b10)));
            a1 = sigm(fmaf(t0, w1.z, fmaf(t1, w1.w, b11)));
            Os[(ty * 8 + i) * 64 + tx * 4 + jj] = fmaf(a0, owv.x, fmaf(a1, owv.y, obv));
        }
    }
    __syncthreads();

    // coalesced write-out: 128 b rows x 64 m = 2048 float4 / 4 ... (64 m = 16 float4)
#pragma unroll
    for (int it = 0; it < 8; it++) {
        int idx = tid + it * 256;           // 0..2047
        int row = idx >> 4, mq = (idx & 15) * 4;
        float4 v = *reinterpret_cast<const float4*>(&Os[row * 64 + mq]);
        *reinterpret_cast<float4*>(&out[out_off + (size_t)(b0 + row) * M_DIM + (n0 >> 1) + mq]) = v;
    }
}

// ===================== launch =====================
extern "C" void kernel_launch(void* const* d_in, const int* in_sizes, int n_in,
                              void* d_out, int out_size)
{
    const float* x        = (const float*)d_in[0];
    const float* eps      = (const float*)d_in[1];
    const float* enc1_w   = (const float*)d_in[2];
    const float* enc1_b   = (const float*)d_in[3];
    const float* enc2_w   = (const float*)d_in[4];
    const float* enc2_b   = (const float*)d_in[5];
    const float* mu_w     = (const float*)d_in[6];
    const float* mu_b     = (const float*)d_in[7];
    const float* lv_w     = (const float*)d_in[8];
    const float* lv_b     = (const float*)d_in[9];
    const float* m_ful_w  = (const float*)d_in[10];
    const float* m_ful_b  = (const float*)d_in[11];
    const float* m_h_w    = (const float*)d_in[12];
    const float* m_h_b    = (const float*)d_in[13];
    const float* m_out_w  = (const float*)d_in[14];
    const float* m_out_b  = (const float*)d_in[15];
    const float* c_ful_w  = (const float*)d_in[16];
    const float* c_ful_b  = (const float*)d_in[17];
    const float* c_h_w    = (const float*)d_in[18];
    const float* c_h_b    = (const float*)d_in[19];
    const float* c_out_w  = (const float*)d_in[20];
    const float* c_out_b  = (const float*)d_in[21];
    float* out = (float*)d_out;

    __half *xh, *w1h, *w2h, *h1h;
    float *h2, *mulv, *z;
    cudaGetSymbolAddress((void**)&xh,   g_xh);
    cudaGetSymbolAddress((void**)&w1h,  g_w1h);
    cudaGetSymbolAddress((void**)&w2h,  g_w2h);
    cudaGetSymbolAddress((void**)&h1h,  g_h1h);
    cudaGetSymbolAddress((void**)&h2,   g_h2);
    cudaGetSymbolAddress((void**)&mulv, g_mulv);
    cudaGetSymbolAddress((void**)&z,    g_z);

    cudaFuncSetAttribute(gemm_h16_kernel<__half, ACT_RELU>,
                         cudaFuncAttributeMaxDynamicSharedMemorySize, SM_GEMM_TOTAL);
    cudaFuncSetAttribute(gemm_h16_kernel<float, ACT_RELU>,
                         cudaFuncAttributeMaxDynamicSharedMemorySize, SM_GEMM_TOTAL);
    cudaFuncSetAttribute(decoder_kernel,
                         cudaFuncAttributeMaxDynamicSharedMemorySize, DEC_SMEM);

    // ---- prep: fp32 -> fp16 (x, enc1_w, enc2_w) in one launch ----
    f2h3_kernel<<<(NX8 + 2 * NW8 + 255) / 256, 256>>>(x, enc1_w, enc2_w, xh, w1h, w2h);

    // ---- encoder GEMMs (mma.sync fp16 path, at its rate ceiling) ----
    dim3 g1(M_DIM / 128, B_DIM / 128);
    gemm_h16_kernel<__half, ACT_RELU><<<g1, 512, SM_GEMM_TOTAL>>>(xh,  w1h, enc1_b, h1h, M_DIM, M_DIM);
    gemm_h16_kernel<float,  ACT_RELU><<<g1, 512, SM_GEMM_TOTAL>>>(h1h, w2h, enc2_b, h2,  M_DIM, M_DIM);

    // ---- mu / logvar projection ----
    cudaMemsetAsync(mulv, 0, B_DIM * 128 * sizeof(float), 0);
    dim3 g2(B_DIM / 64, 4096 / 512);   // (16, 8)
    mulv_kernel<<<g2, 256>>>(h2, mu_w, lv_w, mulv);

    z_kernel<<<(B_DIM * Z_DIM + 255) / 256, 256>>>(mulv, eps, mu_b, lv_b, z, out);

    // ---- fused decoder (both branches) ----
    dim3 g3(H_DIM / 128, B_DIM / 128, 2);   // (64, 8, 2)
    decoder_kernel<<<g3, 256, DEC_SMEM>>>(
        z,
        m_ful_w, m_ful_b, m_h_w, m_h_b, m_out_w, m_out_b,
        c_ful_w, c_ful_b, c_h_w, c_h_b, c_out_w, c_out_b,
        out);
}

// round 8
// speedup vs baseline: 4.7444x; 1.0860x over previous
#include <cuda_runtime.h>
#include <cuda_fp16.h>
#include <cstdint>
#include <cstddef>

// Problem dims (fixed)
#define B_DIM 1024
#define M_DIM 4096
#define W_DIM 2
#define L_DIM 2
#define Z_DIM 64
#define H_DIM 8192   // M*W

// Output layout: x_recon [B*M], logcov [B*M], mu [B*Z], logvar [B*Z]
#define OFF_XREC  0
#define OFF_LCOV  (B_DIM * M_DIM)
#define OFF_MU    (2 * B_DIM * M_DIM)
#define OFF_LV    (2 * B_DIM * M_DIM + B_DIM * Z_DIM)

// -------- scratch (no allocations allowed; __device__ globals) --------
__device__ __half g_xh  [B_DIM * M_DIM];   // x in fp16
__device__ __half g_w1h [M_DIM * M_DIM];   // enc1_w in fp16
__device__ __half g_w2h [M_DIM * M_DIM];   // enc2_w in fp16
__device__ __half g_wch [128 * M_DIM];     // concat(mu_w, lv_w) in fp16
__device__ __half g_h1h [B_DIM * M_DIM];   // encoder layer-1 out (fp16)
__device__ __half g_h2h [B_DIM * M_DIM];   // encoder layer-2 out (fp16)
__device__ float  g_mulv[B_DIM * 128];
__device__ float  g_z[B_DIM * Z_DIM];

__device__ __forceinline__ float sigm(float x) { return 1.0f / (1.0f + expf(-x)); }

#define ACT_NONE 0
#define ACT_RELU 1

// ===================== merged fp32 -> fp16 conversion =====================
// Segments: x (B*M), enc1_w (M*M), enc2_w (M*M), mu_w (64*M), lv_w (64*M).
#define NX8 (B_DIM * M_DIM / 8)
#define NW8 (M_DIM * M_DIM / 8)
#define NC8 (64 * M_DIM / 8)
#define NTOT8 (NX8 + 2 * NW8 + 2 * NC8)

__global__ void __launch_bounds__(256) f2h5_kernel(
    const float* __restrict__ x,  const float* __restrict__ w1,
    const float* __restrict__ w2, const float* __restrict__ muw,
    const float* __restrict__ lvw,
    __half* __restrict__ xh, __half* __restrict__ w1h,
    __half* __restrict__ w2h, __half* __restrict__ wch)
{
    int i = blockIdx.x * 256 + threadIdx.x;
    const float* in; __half* out; int j;
    if (i < NX8)                     { in = x;   out = xh;  j = i; }
    else if (i < NX8 + NW8)          { in = w1;  out = w1h; j = i - NX8; }
    else if (i < NX8 + 2 * NW8)      { in = w2;  out = w2h; j = i - NX8 - NW8; }
    else if (i < NX8 + 2 * NW8 + NC8){ in = muw; out = wch; j = i - NX8 - 2 * NW8; }
    else if (i < NTOT8)              { in = lvw; out = wch + 64 * M_DIM; j = i - NX8 - 2 * NW8 - NC8; }
    else return;
    const float4* p = reinterpret_cast<const float4*>(in) + 2 * (size_t)j;
    float4 a = p[0], b = p[1];
    __half2 h0 = __floats2half2_rn(a.x, a.y);
    __half2 h1 = __floats2half2_rn(a.z, a.w);
    __half2 h2 = __floats2half2_rn(b.x, b.y);
    __half2 h3 = __floats2half2_rn(b.z, b.w);
    uint4 u;
    u.x = *reinterpret_cast<uint32_t*>(&h0);
    u.y = *reinterpret_cast<uint32_t*>(&h1);
    u.z = *reinterpret_cast<uint32_t*>(&h2);
    u.w = *reinterpret_cast<uint32_t*>(&h3);
    reinterpret_cast<uint4*>(out)[j] = u;
}

// ===================== fp16 cp.async tensor-core GEMM =====================
// C = act(A * W^T + bias)  (or split-K: C += A*W^T via atomicAdd)
// A: [Mrows, Kstride] fp16, Wt: [N, Kstride] fp16. CTA 128x128, BK=32,
// 512 threads (16 warps, 32x32 warp tiles), 4-stage cp.async, mma.m16n8k16.

__device__ __forceinline__ uint32_t smem_u32(const void* p) {
    uint32_t a;
    asm("{ .reg .u64 t; cvta.to.shared.u64 t, %1; cvt.u32.u64 %0, t; }" : "=r"(a) : "l"(p));
    return a;
}
__device__ __forceinline__ void ldmx4(uint32_t* r, uint32_t addr) {
    asm volatile("ldmatrix.sync.aligned.m8n8.x4.shared.b16 {%0,%1,%2,%3}, [%4];"
                 : "=r"(r[0]), "=r"(r[1]), "=r"(r[2]), "=r"(r[3]) : "r"(addr));
}
__device__ __forceinline__ void mma_f16(float* d, const uint32_t* a, const uint32_t* b) {
    asm volatile(
        "mma.sync.aligned.m16n8k16.row.col.f32.f16.f16.f32 "
        "{%0,%1,%2,%3}, {%4,%5,%6,%7}, {%8,%9}, {%0,%1,%2,%3};\n"
        : "+f"(d[0]), "+f"(d[1]), "+f"(d[2]), "+f"(d[3])
        : "r"(a[0]), "r"(a[1]), "r"(a[2]), "r"(a[3]), "r"(b[0]), "r"(b[1]));
}
__device__ __forceinline__ void cp_async16(uint32_t smem_addr, const void* gptr) {
    asm volatile("cp.async.cg.shared.global [%0], [%1], 16;\n" :: "r"(smem_addr), "l"(gptr));
}
__device__ __forceinline__ void cp_commit() { asm volatile("cp.async.commit_group;\n"); }
template <int N> __device__ __forceinline__ void cp_wait() {
    asm volatile("cp.async.wait_group %0;\n" :: "n"(N));
}

#define HS_ROW   80
#define HS_TILE  (128 * HS_ROW)
#define HS_STAGE (2 * HS_TILE)
#define N_STAGES 4
#define SM_GEMM_TOTAL (N_STAGES * HS_STAGE)   // 81920 B dynamic

template <typename OT, int ACT, bool SPLITK>
__global__ void __launch_bounds__(512, 2) gemm_h16_kernel(
    const __half* __restrict__ A, const __half* __restrict__ Wt,
    const float* __restrict__ bias, OT* __restrict__ C,
    int Ndim, int Kstride, int Kchunk)
{
    extern __shared__ __align__(16) uint8_t dsm[];
    __shared__ float sbias[128];

    const int tid  = threadIdx.x;
    const int lane = tid & 31;
    const int warp = tid >> 5;
    const int wm   = (warp & 3) * 32;
    const int wn   = (warp >> 2) * 32;
    const int m0   = blockIdx.y * 128;
    const int n0   = blockIdx.x * 128;
    const int koff = SPLITK ? blockIdx.z * Kchunk : 0;
    const uint32_t sb = smem_u32(dsm);

    if (!SPLITK && tid < 128) sbias[tid] = bias[n0 + tid];

    const int rC = tid >> 2;
    const int kC = (tid & 3) * 8;
    const uint32_t dC = (uint32_t)rC * HS_ROW + kC * 2;

    const __half* Ab = A  + (size_t)m0 * Kstride + koff;
    const __half* Bb = Wt + (size_t)n0 * Kstride + koff;

    const int T = Kchunk >> 5;

    auto issue = [&](int it) {
        uint32_t st = sb + (it & (N_STAGES - 1)) * HS_STAGE;
        cp_async16(st + dC,           Ab + (size_t)rC * Kstride + it * 32 + kC);
        cp_async16(st + HS_TILE + dC, Bb + (size_t)rC * Kstride + it * 32 + kC);
        cp_commit();
    };

    const uint32_t a_lm = ((lane & 7) + ((lane >> 3) & 1) * 8) * HS_ROW + ((lane >> 4) & 1) * 16;
    const uint32_t b_lm = ((lane & 7) + ((lane >> 4) & 1) * 8) * HS_ROW + ((lane >> 3) & 1) * 16;

    float acc[2][4][4];
#pragma unroll
    for (int i = 0; i < 2; i++)
#pragma unroll
        for (int j = 0; j < 4; j++)
#pragma unroll
            for (int r = 0; r < 4; r++) acc[i][j][r] = 0.0f;

#pragma unroll
    for (int i = 0; i < N_STAGES - 1; i++) issue(i);

    for (int it = 0; it < T; ++it) {
        cp_wait<N_STAGES - 2>();
        __syncthreads();

        if (it + N_STAGES - 1 < T) issue(it + N_STAGES - 1);
        else cp_commit();

        const uint32_t sa  = sb + (it & (N_STAGES - 1)) * HS_STAGE;
        const uint32_t sbm = sa + HS_TILE;
#pragma unroll
        for (int kk = 0; kk < 2; kk++) {
            uint32_t af[2][4], bf[2][4];
#pragma unroll
            for (int im = 0; im < 2; im++)
                ldmx4(af[im], sa + (wm + im * 16) * HS_ROW + a_lm + kk * 32);
#pragma unroll
            for (int jn = 0; jn < 2; jn++)
                ldmx4(bf[jn], sbm + (wn + jn * 16) * HS_ROW + b_lm + kk * 32);
#pragma unroll
            for (int im = 0; im < 2; im++)
#pragma unroll
                for (int jn = 0; jn < 2; jn++) {
                    mma_f16(acc[im][2 * jn],     af[im], &bf[jn][0]);
                    mma_f16(acc[im][2 * jn + 1], af[im], &bf[jn][2]);
                }
        }
    }

    const int g = lane >> 2, t = lane & 3;
#pragma unroll
    for (int im = 0; im < 2; im++) {
        int r0 = m0 + wm + im * 16 + g;
#pragma unroll
        for (int in_ = 0; in_ < 4; in_++) {
            int cl = wn + in_ * 8 + t * 2;
            int c = n0 + cl;
            if (SPLITK) {
                float* Cf = reinterpret_cast<float*>(C);
                atomicAdd(&Cf[(size_t)r0 * Ndim + c],           acc[im][in_][0]);
                atomicAdd(&Cf[(size_t)r0 * Ndim + c + 1],       acc[im][in_][1]);
                atomicAdd(&Cf[(size_t)(r0 + 8) * Ndim + c],     acc[im][in_][2]);
                atomicAdd(&Cf[(size_t)(r0 + 8) * Ndim + c + 1], acc[im][in_][3]);
            } else {
                float b0v = sbias[cl], b1v = sbias[cl + 1];
                float v00 = acc[im][in_][0] + b0v;
                float v01 = acc[im][in_][1] + b1v;
                float v10 = acc[im][in_][2] + b0v;
                float v11 = acc[im][in_][3] + b1v;
                if (ACT == ACT_RELU) {
                    v00 = fmaxf(v00, 0.0f); v01 = fmaxf(v01, 0.0f);
                    v10 = fmaxf(v10, 0.0f); v11 = fmaxf(v11, 0.0f);
                }
                if (sizeof(OT) == 2) {
                    __half* Ch = reinterpret_cast<__half*>(C);
                    __half2 lo = __floats2half2_rn(v00, v01);
                    __half2 hi = __floats2half2_rn(v10, v11);
                    *reinterpret_cast<__half2*>(&Ch[(size_t)r0 * Ndim + c]) = lo;
                    *reinterpret_cast<__half2*>(&Ch[(size_t)(r0 + 8) * Ndim + c]) = hi;
                } else {
                    float* Cf = reinterpret_cast<float*>(C);
                    *reinterpret_cast<float2*>(&Cf[(size_t)r0 * Ndim + c]) = make_float2(v00, v01);
                    *reinterpret_cast<float2*>(&Cf[(size_t)(r0 + 8) * Ndim + c]) = make_float2(v10, v11);
                }
            }
        }
    }
}

// ===================== reparameterization + mu/logvar output =====================
__global__ void z_kernel(const float* __restrict__ mulv, const float* __restrict__ eps,
                         const float* __restrict__ mu_b, const float* __restrict__ lv_b,
                         float* __restrict__ z, float* __restrict__ out)
{
    int idx = blockIdx.x * 256 + threadIdx.x;
    if (idx >= B_DIM * Z_DIM) return;
    int b = idx >> 6, j = idx & 63;
    float mu = mulv[(size_t)b * 128 + j]      + mu_b[j];
    float lv = mulv[(size_t)b * 128 + 64 + j] + lv_b[j];
    z[idx] = mu + expf(0.5f * lv) * eps[idx];
    out[OFF_MU + idx] = mu;
    out[OFF_LV + idx] = lv;
}

// ===================== fused decoder: fulcon GEMM + block-diag layers + output =======
#define DEC_SMEM (2 * 64 * 132 * 4)    // 67584 B

__global__ void __launch_bounds__(256) decoder_kernel(
    const float* __restrict__ z,
    const float* __restrict__ m_ful_w, const float* __restrict__ m_ful_b,
    const float* __restrict__ m_h_w,   const float* __restrict__ m_h_b,
    const float* __restrict__ m_out_w, const float* __restrict__ m_out_b,
    const float* __restrict__ c_ful_w, const float* __restrict__ c_ful_b,
    const float* __restrict__ c_h_w,   const float* __restrict__ c_h_b,
    const float* __restrict__ c_out_w, const float* __restrict__ c_out_b,
    float* __restrict__ out)
{
    extern __shared__ float ds[];
    float* Zs = ds;               // [64 k][132]
    float* Ws = ds + 64 * 132;    // [64 k][132]
    __shared__ float sfb[128];

    const bool mean = (blockIdx.z == 0);
    const float* fw = mean ? m_ful_w : c_ful_w;
    const float* fb = mean ? m_ful_b : c_ful_b;
    const float* hw = mean ? m_h_w   : c_h_w;
    const float* hb = mean ? m_h_b   : c_h_b;
    const float* ow = mean ? m_out_w : c_out_w;
    const float* ob = mean ? m_out_b : c_out_b;
    const int out_off = mean ? OFF_XREC : OFF_LCOV;

    const int tid = threadIdx.x;
    const int tx  = tid & 15;
    const int ty  = tid >> 4;
    const int n0  = blockIdx.x * 128;
    const int b0  = blockIdx.y * 128;

#pragma unroll
    for (int it = 0; it < 8; it++) {
        int idx = tid + it * 256;
        int row = idx >> 4, kq = (idx & 15) * 4;
        float4 v = *reinterpret_cast<const float4*>(&z[(size_t)(b0 + row) * 64 + kq]);
        Zs[(kq + 0) * 132 + row] = v.x; Zs[(kq + 1) * 132 + row] = v.y;
        Zs[(kq + 2) * 132 + row] = v.z; Zs[(kq + 3) * 132 + row] = v.w;
    }
#pragma unroll
    for (int it = 0; it < 8; it++) {
        int idx = tid + it * 256;
        int row = idx >> 4, kq = (idx & 15) * 4;
        float4 v = *reinterpret_cast<const float4*>(&fw[(size_t)(n0 + row) * 64 + kq]);
        Ws[(kq + 0) * 132 + row] = v.x; Ws[(kq + 1) * 132 + row] = v.y;
        Ws[(kq + 2) * 132 + row] = v.z; Ws[(kq + 3) * 132 + row] = v.w;
    }
    if (tid < 128) sfb[tid] = fb[n0 + tid];
    __syncthreads();

    float acc[8][8];
#pragma unroll
    for (int i = 0; i < 8; i++)
#pragma unroll
        for (int j = 0; j < 8; j++) acc[i][j] = 0.0f;

#pragma unroll 4
    for (int k = 0; k < 64; k++) {
        float ar[8], br[8];
        *reinterpret_cast<float4*>(&ar[0]) = *reinterpret_cast<const float4*>(&Zs[k * 132 + ty * 8]);
        *reinterpret_cast<float4*>(&ar[4]) = *reinterpret_cast<const float4*>(&Zs[k * 132 + ty * 8 + 4]);
        *reinterpret_cast<float4*>(&br[0]) = *reinterpret_cast<const float4*>(&Ws[k * 132 + tx * 8]);
        *reinterpret_cast<float4*>(&br[4]) = *reinterpret_cast<const float4*>(&Ws[k * 132 + tx * 8 + 4]);
#pragma unroll
        for (int i = 0; i < 8; i++)
#pragma unroll
            for (int j = 0; j < 8; j++)
                acc[i][j] = fmaf(ar[i], br[j], acc[i][j]);
    }
#pragma unroll
    for (int i = 0; i < 8; i++)
#pragma unroll
        for (int j = 0; j < 8; j++)
            acc[i][j] = sigm(acc[i][j] + sfb[tx * 8 + j]);

    __syncthreads();
    float* Os = ds;    // [128 b][64 m]

#pragma unroll
    for (int jj = 0; jj < 4; jj++) {
        int m = (n0 >> 1) + tx * 4 + jj;
        float4 w0 = *reinterpret_cast<const float4*>(&hw[(size_t)m * 4]);
        float4 w1 = *reinterpret_cast<const float4*>(&hw[((size_t)M_DIM + m) * 4]);
        float b00 = hb[2 * m],          b01 = hb[2 * m + 1];
        float b10 = hb[H_DIM + 2 * m],  b11 = hb[H_DIM + 2 * m + 1];
        float2 owv = *reinterpret_cast<const float2*>(&ow[2 * m]);
        float obv = ob[m];
#pragma unroll
        for (int i = 0; i < 8; i++) {
            float a0 = acc[i][2 * jj], a1 = acc[i][2 * jj + 1];
            float t0 = sigm(fmaf(a0, w0.x, fmaf(a1, w0.y, b00)));
            float t1 = sigm(fmaf(a0, w0.z, fmaf(a1, w0.w, b01)));
            a0 = sigm(fmaf(t0, w1.x, fmaf(t1, w1.y, b10)));
            a1 = sigm(fmaf(t0, w1.z, fmaf(t1, w1.w, b11)));
            Os[(ty * 8 + i) * 64 + tx * 4 + jj] = fmaf(a0, owv.x, fmaf(a1, owv.y, obv));
        }
    }
    __syncthreads();

#pragma unroll
    for (int it = 0; it < 8; it++) {
        int idx = tid + it * 256;
        int row = idx >> 4, mq = (idx & 15) * 4;
        float4 v = *reinterpret_cast<const float4*>(&Os[row * 64 + mq]);
        *reinterpret_cast<float4*>(&out[out_off + (size_t)(b0 + row) * M_DIM + (n0 >> 1) + mq]) = v;
    }
}

// ===================== launch =====================
extern "C" void kernel_launch(void* const* d_in, const int* in_sizes, int n_in,
                              void* d_out, int out_size)
{
    const float* x        = (const float*)d_in[0];
    const float* eps      = (const float*)d_in[1];
    const float* enc1_w   = (const float*)d_in[2];
    const float* enc1_b   = (const float*)d_in[3];
    const float* enc2_w   = (const float*)d_in[4];
    const float* enc2_b   = (const float*)d_in[5];
    const float* mu_w     = (const float*)d_in[6];
    const float* mu_b     = (const float*)d_in[7];
    const float* lv_w     = (const float*)d_in[8];
    const float* lv_b     = (const float*)d_in[9];
    const float* m_ful_w  = (const float*)d_in[10];
    const float* m_ful_b  = (const float*)d_in[11];
    const float* m_h_w    = (const float*)d_in[12];
    const float* m_h_b    = (const float*)d_in[13];
    const float* m_out_w  = (const float*)d_in[14];
    const float* m_out_b  = (const float*)d_in[15];
    const float* c_ful_w  = (const float*)d_in[16];
    const float* c_ful_b  = (const float*)d_in[17];
    const float* c_h_w    = (const float*)d_in[18];
    const float* c_h_b    = (const float*)d_in[19];
    const float* c_out_w  = (const float*)d_in[20];
    const float* c_out_b  = (const float*)d_in[21];
    float* out = (float*)d_out;

    __half *xh, *w1h, *w2h, *wch, *h1h, *h2h;
    float *mulv, *z;
    cudaGetSymbolAddress((void**)&xh,   g_xh);
    cudaGetSymbolAddress((void**)&w1h,  g_w1h);
    cudaGetSymbolAddress((void**)&w2h,  g_w2h);
    cudaGetSymbolAddress((void**)&wch,  g_wch);
    cudaGetSymbolAddress((void**)&h1h,  g_h1h);
    cudaGetSymbolAddress((void**)&h2h,  g_h2h);
    cudaGetSymbolAddress((void**)&mulv, g_mulv);
    cudaGetSymbolAddress((void**)&z,    g_z);

    cudaFuncSetAttribute((const void*)gemm_h16_kernel<__half, ACT_RELU, false>,
                         cudaFuncAttributeMaxDynamicSharedMemorySize, SM_GEMM_TOTAL);
    cudaFuncSetAttribute((const void*)gemm_h16_kernel<float, ACT_NONE, true>,
                         cudaFuncAttributeMaxDynamicSharedMemorySize, SM_GEMM_TOTAL);
    cudaFuncSetAttribute((const void*)decoder_kernel,
                         cudaFuncAttributeMaxDynamicSharedMemorySize, DEC_SMEM);

    // ---- prep: fp32 -> fp16 (x, enc1_w, enc2_w, mu_w|lv_w) in one launch ----
    f2h5_kernel<<<(NTOT8 + 255) / 256, 256>>>(x, enc1_w, enc2_w, mu_w, lv_w,
                                              xh, w1h, w2h, wch);

    // ---- encoder GEMMs (mma.sync fp16 path, at its rate ceiling) ----
    dim3 g1(M_DIM / 128, B_DIM / 128);
    gemm_h16_kernel<__half, ACT_RELU, false><<<g1, 512, SM_GEMM_TOTAL>>>(
        xh,  w1h, enc1_b, h1h, M_DIM, M_DIM, M_DIM);
    gemm_h16_kernel<__half, ACT_RELU, false><<<g1, 512, SM_GEMM_TOTAL>>>(
        h1h, w2h, enc2_b, h2h, M_DIM, M_DIM, M_DIM);

    // ---- mu / logvar projection: split-K tensor GEMM (atomic accumulate) ----
    cudaMemsetAsync(mulv, 0, B_DIM * 128 * sizeof(float), 0);
    dim3 g2(1, B_DIM / 128, 16);   // N=128 tile, 8 M-tiles, 16 K-chunks of 256
    gemm_h16_kernel<float, ACT_NONE, true><<<g2, 512, SM_GEMM_TOTAL>>>(
        h2h, wch, nullptr, mulv, 128, M_DIM, 256);

    z_kernel<<<(B_DIM * Z_DIM + 255) / 256, 256>>>(mulv, eps, mu_b, lv_b, z, out);

    // ---- fused decoder (both branches) ----
    dim3 g3(H_DIM / 128, B_DIM / 128, 2);
    decoder_kernel<<<g3, 256, DEC_SMEM>>>(
        z,
        m_ful_w, m_ful_b, m_h_w, m_h_b, m_out_w, m_out_b,
        c_ful_w, c_ful_b, c_h_w, c_h_b, c_out_w, c_out_b,
        out);
}